// round 13
// baseline (speedup 1.0000x reference)
#include <cuda_runtime.h>
#include <cuda_fp16.h>
#include <cstdint>

#define T_ 8192
#define D_ 1024
#define H_ 1024
#define E_ 8
#define B_ 4
#define S_ 2048

#define BM 128
#define SSZ 32768u    // stage: A 16KB + B 16KB (BK=64)
#define NCH 16        // 1024 / 64

// ---------------- scratch (no allocation allowed) ----------------
__device__ int g_cnt[E_];
__device__ int g_base[E_];
__device__ int g_done_gate;
__device__ int g_done_ffn2;
__device__ int g_btok[E_ * T_];
__device__ float g_bwt[E_ * T_];
__device__ unsigned char g_nonpad[T_];
__device__ float g_invcnt[B_];
__device__ float g_mean[E_ * B_ * D_];
// fp16 scratch
__device__ uint16_t g_xf[(size_t)T_ * D_];
__device__ uint16_t g_w1f[(size_t)E_ * D_ * H_];
__device__ uint16_t g_w3f[(size_t)E_ * D_ * H_];
__device__ uint16_t g_w2f[(size_t)E_ * H_ * D_];
__device__ uint16_t g_hactf[(size_t)2 * T_ * H_];

// ================= helpers =================
__device__ __forceinline__ uint32_t smem_u32(const void* p) {
    uint32_t a;
    asm("{ .reg .u64 t; cvta.to.shared.u64 t, %1; cvt.u32.u64 %0, t; }" : "=r"(a) : "l"(p));
    return a;
}
__device__ __forceinline__ uint32_t cvt1h(float f0, float f1) {
    uint32_t h;
    asm("cvt.rn.f16x2.f32 %0, %1, %2;" : "=r"(h) : "f"(f1), "f"(f0));
    return h;
}
__device__ __forceinline__ void cpa16(uint32_t dst, const void* src) {
    asm volatile("cp.async.cg.shared.global [%0], [%1], 16;" :: "r"(dst), "l"(src));
}
#define CP_COMMIT() asm volatile("cp.async.commit_group;")
#define CP_WAIT1() asm volatile("cp.async.wait_group 1;")
__device__ __forceinline__ void ldsm4(uint32_t* r, uint32_t a) {
    asm volatile("ldmatrix.sync.aligned.m8n8.x4.shared.b16 {%0,%1,%2,%3}, [%4];"
                 : "=r"(r[0]), "=r"(r[1]), "=r"(r[2]), "=r"(r[3]) : "r"(a));
}
__device__ __forceinline__ void ldsm4t(uint32_t* r, uint32_t a) {
    asm volatile("ldmatrix.sync.aligned.m8n8.x4.trans.shared.b16 {%0,%1,%2,%3}, [%4];"
                 : "=r"(r[0]), "=r"(r[1]), "=r"(r[2]), "=r"(r[3]) : "r"(a));
}
__device__ __forceinline__ void mma16816h(float* d, const uint32_t* a, uint32_t b0, uint32_t b1) {
    asm volatile(
        "mma.sync.aligned.m16n8k16.row.col.f32.f16.f16.f32 "
        "{%0,%1,%2,%3},{%4,%5,%6,%7},{%8,%9},{%0,%1,%2,%3};"
        : "+f"(d[0]), "+f"(d[1]), "+f"(d[2]), "+f"(d[3])
        : "r"(a[0]), "r"(a[1]), "r"(a[2]), "r"(a[3]), "r"(b0), "r"(b1));
}
__device__ __forceinline__ uint32_t off128(int r, int u) {
    return (uint32_t)(r * 128 + ((u ^ (r & 7)) << 4));
}
__device__ __forceinline__ uint32_t off256(int r, int u) {
    return (uint32_t)(r * 256 + ((((u ^ r) & 7) | (u & 8)) << 4));
}

// ---------------- fused weight convert, 4 coalesced float4 per thread ----------------
#define SEG_ (2097152u)   // float4 count per tensor
__global__ void wconvert_kernel(const float* __restrict__ w1, const float* __restrict__ w3,
                                const float* __restrict__ w2) {
    uint32_t base = blockIdx.x * 1024 + threadIdx.x;
#pragma unroll
    for (int k = 0; k < 4; k++) {
        uint32_t idx = base + k * 256;
        uint32_t seg = idx / SEG_, off = idx % SEG_;
        const float4* s = (const float4*)((seg == 0) ? w1 : (seg == 1) ? w3 : w2);
        uint2* d = (uint2*)((seg == 0) ? g_w1f : (seg == 1) ? g_w3f : g_w2f);
        float4 v = s[off];
        d[off] = make_uint2(cvt1h(v.x, v.y), cvt1h(v.z, v.w));
    }
}

// ---------------- prep ----------------
__global__ void prep_kernel(const unsigned char* __restrict__ pad,
                            const unsigned char* __restrict__ mid) {
    __shared__ int onebyte;
    __shared__ int cnts[B_];
    int tid = threadIdx.x;
    if (tid == 0) { onebyte = 0; g_done_gate = 0; g_done_ffn2 = 0; }
    if (tid < B_) cnts[tid] = 0;
    if (tid < E_) g_cnt[tid] = 0;
    __syncthreads();
    int found = 0;
    for (int i = tid; i < 2048; i += 256)
        if (pad[4 * i + 1]) found = 1;
    if (found) onebyte = 1;
    __syncthreads();
    bool b1 = (onebyte != 0);
    const unsigned int* pw = (const unsigned int*)pad;
    const unsigned int* mw = (const unsigned int*)mid;
    for (int t = tid; t < T_; t += 256) {
        bool p = b1 ? (pad[t] != 0) : (pw[t] != 0);
        bool m = b1 ? (mid[t] != 0) : (mw[t] != 0);
        unsigned char np = (!p && !m) ? 1 : 0;
        g_nonpad[t] = np;
        if (np) atomicAdd(&cnts[t >> 11], 1);
    }
    for (int i = tid; i < E_ * B_ * D_; i += 256) g_mean[i] = 0.f;
    __syncthreads();
    if (tid < B_) g_invcnt[tid] = 1.f / (float)cnts[tid];
}

// ---------------- gating + x fp16 conversion + (last block) bucket prefix ----------------
__global__ void xgate_kernel(const float* __restrict__ x,
                             const float* __restrict__ gw,
                             float* __restrict__ route_out) {
    __shared__ int isLast;
    int warp = threadIdx.x >> 5, lane = threadIdx.x & 31;
    int t = blockIdx.x * 8 + warp;
    const float* xr = x + (size_t)t * D_;
    float acc[8];
#pragma unroll
    for (int e = 0; e < 8; e++) acc[e] = 0.f;
    for (int d = lane; d < D_; d += 32) {
        float xv = xr[d];
        float4 g0 = *(const float4*)(gw + (size_t)d * 8);
        float4 g1 = *(const float4*)(gw + (size_t)d * 8 + 4);
        acc[0] += xv * g0.x; acc[1] += xv * g0.y;
        acc[2] += xv * g0.z; acc[3] += xv * g0.w;
        acc[4] += xv * g1.x; acc[5] += xv * g1.y;
        acc[6] += xv * g1.z; acc[7] += xv * g1.w;
    }
#pragma unroll
    for (int o = 16; o; o >>= 1)
#pragma unroll
        for (int e = 0; e < 8; e++)
            acc[e] += __shfl_xor_sync(0xffffffffu, acc[e], o);
    if (lane == 0) {
        float mx = acc[0];
#pragma unroll
        for (int e = 1; e < 8; e++) mx = fmaxf(mx, acc[e]);
        float p[8], s = 0.f;
#pragma unroll
        for (int e = 0; e < 8; e++) { p[e] = __expf(acc[e] - mx); s += p[e]; }
        float inv = 1.f / s;
#pragma unroll
        for (int e = 0; e < 8; e++) p[e] *= inv;
        float* ro = route_out + (size_t)t * 8;
#pragma unroll
        for (int e = 0; e < 8; e++) ro[e] = p[e];
        int e0 = 0;
#pragma unroll
        for (int e = 1; e < 8; e++) if (p[e] > p[e0]) e0 = e;
        int e1 = (e0 == 0) ? 1 : 0;
#pragma unroll
        for (int e = 0; e < 8; e++) if (e != e0 && p[e] > p[e1]) e1 = e;
        float inv2 = 1.f / (p[e0] + p[e1]);
        int s0 = atomicAdd(&g_cnt[e0], 1);
        g_btok[e0 * T_ + s0] = t; g_bwt[e0 * T_ + s0] = p[e0] * inv2;
        int s1 = atomicAdd(&g_cnt[e1], 1);
        g_btok[e1 * T_ + s1] = t; g_bwt[e1 * T_ + s1] = p[e1] * inv2;
    }
    size_t base4 = (size_t)blockIdx.x * 2048;
#pragma unroll
    for (int k = 0; k < 8; k++) {
        size_t i = base4 + threadIdx.x + k * 256;
        float4 v = ((const float4*)x)[i];
        ((uint2*)g_xf)[i] = make_uint2(cvt1h(v.x, v.y), cvt1h(v.z, v.w));
    }
    // ---- last block computes bucket prefix (replaces scan_kernel) ----
    __threadfence();
    __syncthreads();
    if (threadIdx.x == 0)
        isLast = (atomicAdd(&g_done_gate, 1) == (int)gridDim.x - 1);
    __syncthreads();
    if (isLast && threadIdx.x == 0) {
        int a = 0;
        for (int e = 0; e < E_; e++) { g_base[e] = a; a += g_cnt[e]; }
    }
}

// ============ ffn1: hact = silu(X@w1)*(X@w3), fp16, BK=64, 3-stage, 2 CTAs/SM ============
__global__ __launch_bounds__(256, 2) void ffn1_mma(int dummy) {
    extern __shared__ char dyn[];
    __shared__ int toks[BM];
    int e = blockIdx.y >> 6, mt = blockIdx.y & 63;
    int cnt = g_cnt[e];
    int row0 = mt * BM;
    if (row0 >= cnt) return;
    int rows = min(BM, cnt - row0);
    int n0 = blockIdx.x * 64;
    int tid = threadIdx.x, wid = tid >> 5, lane = tid & 31;
    if (tid < BM)
        toks[tid] = (tid < rows) ? g_btok[e * T_ + row0 + tid] : g_btok[e * T_ + row0];
    __syncthreads();
    uint32_t sb = (smem_u32(dyn) + 1023u) & ~1023u;

    int am = tid >> 1, ub = (tid & 1) * 4;
    const uint16_t* pA = g_xf + (size_t)toks[am] * D_ + (tid & 1) * 32;
    uint32_t dA[4] = { off128(am, ub), off128(am, ub + 1), off128(am, ub + 2), off128(am, ub + 3) };
    int bk = tid >> 2, bu = (tid & 3) * 2;
    size_t woff = ((size_t)e * D_ + bk) * H_ + n0 + bu * 8;
    const uint16_t* p1 = g_w1f + woff;
    const uint16_t* p3 = g_w3f + woff;
    uint32_t dB0 = off128(bk, bu), dB1 = off128(bk, bu + 1);

    auto issue = [&](int c) {
        uint32_t st = sb + (uint32_t)(c % 3) * SSZ;
        const uint16_t* a = pA + c * 64;
#pragma unroll
        for (int j = 0; j < 4; j++) cpa16(st + dA[j], a + j * 8);
        size_t wo = (size_t)c * 64 * H_;
        cpa16(st + 16384u + dB0, p1 + wo);
        cpa16(st + 16384u + dB1, p1 + wo + 8);
        cpa16(st + 24576u + dB0, p3 + wo);
        cpa16(st + 24576u + dB1, p3 + wo + 8);
        CP_COMMIT();
    };

    float acc1[2][4][4], acc3[2][4][4];
#pragma unroll
    for (int a = 0; a < 2; a++)
#pragma unroll
        for (int b = 0; b < 4; b++)
#pragma unroll
            for (int q = 0; q < 4; q++) { acc1[a][b][q] = 0.f; acc3[a][b][q] = 0.f; }

    int lr = (lane & 7) + ((lane >> 3) & 1) * 8;
    int uo = (lane >> 4) & 1;
    int mq = wid & 3, nh = wid >> 2;

    issue(0); issue(1);
    for (int c = 0; c < NCH; c++) {
        CP_WAIT1();
        __syncthreads();
        if (c + 2 < NCH) issue(c + 2); else CP_COMMIT();
        uint32_t base = sb + (uint32_t)(c % 3) * SSZ;
        uint32_t aT = base, w1T = base + 16384u, w3T = base + 24576u;
#pragma unroll
        for (int kb = 0; kb < 4; kb++) {
            uint32_t A[2][4];
#pragma unroll
            for (int mb = 0; mb < 2; mb++)
                ldsm4(A[mb], aT + off128(mq * 32 + mb * 16 + lr, kb * 2 + uo));
            int krow = kb * 16 + lr;
#pragma unroll
            for (int nb = 0; nb < 2; nb++) {
                uint32_t so = off128(krow, nh * 4 + nb * 2 + uo);
                uint32_t F[4];
                ldsm4t(F, w1T + so);
#pragma unroll
                for (int mb = 0; mb < 2; mb++) {
                    mma16816h(acc1[mb][nb * 2 + 0], A[mb], F[0], F[1]);
                    mma16816h(acc1[mb][nb * 2 + 1], A[mb], F[2], F[3]);
                }
                ldsm4t(F, w3T + so);
#pragma unroll
                for (int mb = 0; mb < 2; mb++) {
                    mma16816h(acc3[mb][nb * 2 + 0], A[mb], F[0], F[1]);
                    mma16816h(acc3[mb][nb * 2 + 1], A[mb], F[2], F[3]);
                }
            }
        }
    }
    int gbase = g_base[e] + row0;
    int r0c = lane >> 2, cc = 2 * (lane & 3);
#pragma unroll
    for (int mb = 0; mb < 2; mb++)
#pragma unroll
        for (int nf = 0; nf < 4; nf++) {
            int col = n0 + nh * 32 + nf * 8 + cc;
#pragma unroll
            for (int hrow = 0; hrow < 2; hrow++) {
                int m0 = mq * 32 + mb * 16 + r0c + hrow * 8;
                if (m0 < rows) {
                    float a0 = acc1[mb][nf][hrow * 2],     b0 = acc3[mb][nf][hrow * 2];
                    float a1 = acc1[mb][nf][hrow * 2 + 1], b1 = acc3[mb][nf][hrow * 2 + 1];
                    float o0 = a0 / (1.f + __expf(-a0)) * b0;
                    float o1 = a1 / (1.f + __expf(-a1)) * b1;
                    size_t off = ((size_t)(gbase + m0) * H_ + col) >> 1;
                    ((uint32_t*)g_hactf)[off] = cvt1h(o0, o1);
                }
            }
        }
}

// ============ ffn2: Y = hact @ w2, fp16, BK=64, 3-stage, 2 CTAs/SM + (last CTA) classifier ============
__global__ __launch_bounds__(256, 2) void ffn2_mma(float* __restrict__ outF,
                                                   const float* __restrict__ clf_w,
                                                   const float* __restrict__ clf_b,
                                                   float* __restrict__ outL) {
    extern __shared__ char dyn[];
    __shared__ int toks[BM];
    __shared__ float wts[BM];
    __shared__ int isLast;
    __shared__ float dots[32];
    int e = blockIdx.y >> 6, mt = blockIdx.y & 63;
    int cnt = g_cnt[e];
    int row0 = mt * BM;
    int tid = threadIdx.x, wid = tid >> 5, lane = tid & 31;
    bool active = (row0 < cnt);
    if (active) {
        int rows = min(BM, cnt - row0);
        int n0 = blockIdx.x * 128;
        if (tid < BM) {
            int idx = e * T_ + row0 + tid;
            toks[tid] = (tid < rows) ? g_btok[idx] : 0;
            wts[tid] = (tid < rows) ? g_bwt[idx] : 0.f;
        }
        __syncthreads();
        uint32_t sb = (smem_u32(dyn) + 1023u) & ~1023u;
        int gbase = g_base[e] + row0;

        int am = tid >> 1, ub = (tid & 1) * 4;
        const uint16_t* pA = g_hactf + (size_t)(gbase + min(am, rows - 1)) * H_ + (tid & 1) * 32;
        uint32_t dA[4] = { off128(am, ub), off128(am, ub + 1), off128(am, ub + 2), off128(am, ub + 3) };
        int bk = tid >> 2, bu4 = (tid & 3) * 4;
        size_t woff = ((size_t)e * H_ + bk) * D_ + n0 + bu4 * 8;
        const uint16_t* p2 = g_w2f + woff;
        uint32_t dB[4] = { off256(bk, bu4), off256(bk, bu4 + 1), off256(bk, bu4 + 2), off256(bk, bu4 + 3) };

        auto issue = [&](int c) {
            uint32_t st = sb + (uint32_t)(c % 3) * SSZ;
            const uint16_t* a = pA + c * 64;
#pragma unroll
            for (int j = 0; j < 4; j++) cpa16(st + dA[j], a + j * 8);
            size_t wo = (size_t)c * 64 * D_;
#pragma unroll
            for (int j = 0; j < 4; j++) cpa16(st + 16384u + dB[j], p2 + wo + j * 8);
            CP_COMMIT();
        };

        float acc[2][8][4];
#pragma unroll
        for (int a = 0; a < 2; a++)
#pragma unroll
            for (int b = 0; b < 8; b++)
#pragma unroll
                for (int q = 0; q < 4; q++) acc[a][b][q] = 0.f;

        int lr = (lane & 7) + ((lane >> 3) & 1) * 8;
        int uo = (lane >> 4) & 1;
        int mq = wid & 3, nh = wid >> 2;

        issue(0); issue(1);
        for (int c = 0; c < NCH; c++) {
            CP_WAIT1();
            __syncthreads();
            if (c + 2 < NCH) issue(c + 2); else CP_COMMIT();
            uint32_t base = sb + (uint32_t)(c % 3) * SSZ;
            uint32_t aT = base, w2T = base + 16384u;
#pragma unroll
            for (int kb = 0; kb < 4; kb++) {
                uint32_t A[2][4];
#pragma unroll
                for (int mb = 0; mb < 2; mb++)
                    ldsm4(A[mb], aT + off128(mq * 32 + mb * 16 + lr, kb * 2 + uo));
                int krow = kb * 16 + lr;
#pragma unroll
                for (int nb = 0; nb < 4; nb++) {
                    uint32_t F[4];
                    ldsm4t(F, w2T + off256(krow, nh * 8 + nb * 2 + uo));
#pragma unroll
                    for (int mb = 0; mb < 2; mb++) {
                        mma16816h(acc[mb][nb * 2 + 0], A[mb], F[0], F[1]);
                        mma16816h(acc[mb][nb * 2 + 1], A[mb], F[2], F[3]);
                    }
                }
            }
        }
        int r0c = lane >> 2, cc = 2 * (lane & 3);
#pragma unroll
        for (int mb = 0; mb < 2; mb++)
#pragma unroll
            for (int nf = 0; nf < 8; nf++) {
                int col = n0 + nh * 64 + nf * 8 + cc;
#pragma unroll
                for (int hrow = 0; hrow < 2; hrow++) {
                    int m0 = mq * 32 + mb * 16 + r0c + hrow * 8;
                    if (m0 < rows) {
                        int t = toks[m0];
                        float wt = wts[m0];
                        float v0 = wt * acc[mb][nf][hrow * 2];
                        float v1 = wt * acc[mb][nf][hrow * 2 + 1];
                        float* fo = outF + (size_t)t * D_ + col;
                        atomicAdd(fo, v0);
                        atomicAdd(fo + 1, v1);
                        if (g_nonpad[t]) {
                            float* mp = g_mean + (size_t)(e * B_ + (t >> 11)) * D_ + col;
                            atomicAdd(mp, v0);
                            atomicAdd(mp + 1, v1);
                        }
                    }
                }
            }
    }
    // ---- ticket; last CTA runs the classifier (replaces clf_kernel) ----
    __threadfence();
    __syncthreads();
    if (tid == 0)
        isLast = (atomicAdd(&g_done_ffn2, 1) == (int)(gridDim.x * gridDim.y) - 1);
    __syncthreads();
    if (isLast) {
        for (int w = wid; w < 32; w += 8) {
            const float* m = g_mean + (size_t)w * D_;
            float s = 0.f;
            for (int d = lane; d < D_; d += 32) s += m[d] * clf_w[d];
#pragma unroll
            for (int o = 16; o; o >>= 1) s += __shfl_xor_sync(0xffffffffu, s, o);
            if (lane == 0) dots[w] = s;
        }
        __syncthreads();
        if (tid < 32) {
            int ee = tid >> 2, bb = tid & 3;
            float c = 0.f;
            for (int k = 0; k <= ee; k++) c += dots[k * 4 + bb];
            outL[ee * B_ + bb] = c * g_invcnt[bb] + clf_b[0];
        }
    }
}

// ---------------- launch ----------------
extern "C" void kernel_launch(void* const* d_in, const int* in_sizes, int n_in,
                              void* d_out, int out_size) {
    int base = 4;
    if (n_in == 9 || (n_in > 3 && in_sizes[3] != 1)) base = 3;
    const float* x = (const float*)d_in[0];
    const unsigned char* pad = (const unsigned char*)d_in[1];
    const unsigned char* mid = (const unsigned char*)d_in[2];
    const float* gw = (const float*)d_in[base + 0];
    const float* w1 = (const float*)d_in[base + 1];
    const float* w2 = (const float*)d_in[base + 2];
    const float* w3 = (const float*)d_in[base + 3];
    const float* cw = (const float*)d_in[base + 4];
    const float* cb = (const float*)d_in[base + 5];
    float* out = (float*)d_out;

    float* out_final = out;
    float* out_logits = out + (size_t)T_ * D_;
    float* out_route = out + (size_t)T_ * D_ + E_ * B_;

    const int smem = 3 * (int)SSZ + 1024;   // 99328 -> 2 CTAs/SM
    cudaFuncSetAttribute(ffn1_mma, cudaFuncAttributeMaxDynamicSharedMemorySize, smem);
    cudaFuncSetAttribute(ffn2_mma, cudaFuncAttributeMaxDynamicSharedMemorySize, smem);

    cudaMemsetAsync(out_final, 0, (size_t)T_ * D_ * sizeof(float), 0);
    wconvert_kernel<<<6144, 256>>>(w1, w3, w2);
    prep_kernel<<<1, 256>>>(pad, mid);
    xgate_kernel<<<T_ / 8, 256>>>(x, gw, out_route);
    ffn1_mma<<<dim3(H_ / 64, E_ * 64), 256, smem>>>(0);
    ffn2_mma<<<dim3(D_ / 128, E_ * 64), 256, smem>>>(out_final, cw, cb, out_logits);
}

// round 14
// speedup vs baseline: 1.1850x; 1.1850x over previous
#include <cuda_runtime.h>
#include <cuda_fp16.h>
#include <cstdint>

#define T_ 8192
#define D_ 1024
#define H_ 1024
#define E_ 8
#define B_ 4
#define S_ 2048

#define BM 128
#define SSZ 32768u    // stage: A 16KB + B 16KB (BK=64)
#define NCH 16        // 1024 / 64

// ---------------- scratch (no allocation allowed) ----------------
__device__ int g_cnt[E_];
__device__ int g_base[E_];
__device__ int g_btok[E_ * T_];
__device__ float g_bwt[E_ * T_];
__device__ unsigned char g_nonpad[T_];
__device__ float g_invcnt[B_];
__device__ float g_mean[E_ * B_ * D_];
// fp16 scratch
__device__ uint16_t g_xf[(size_t)T_ * D_];
__device__ uint16_t g_w1f[(size_t)E_ * D_ * H_];
__device__ uint16_t g_w3f[(size_t)E_ * D_ * H_];
__device__ uint16_t g_w2f[(size_t)E_ * H_ * D_];
__device__ uint16_t g_hactf[(size_t)2 * T_ * H_];

// ================= helpers =================
__device__ __forceinline__ uint32_t smem_u32(const void* p) {
    uint32_t a;
    asm("{ .reg .u64 t; cvta.to.shared.u64 t, %1; cvt.u32.u64 %0, t; }" : "=r"(a) : "l"(p));
    return a;
}
__device__ __forceinline__ uint32_t cvt1h(float f0, float f1) {
    uint32_t h;
    asm("cvt.rn.f16x2.f32 %0, %1, %2;" : "=r"(h) : "f"(f1), "f"(f0));
    return h;
}
__device__ __forceinline__ void cpa16(uint32_t dst, const void* src) {
    asm volatile("cp.async.cg.shared.global [%0], [%1], 16;" :: "r"(dst), "l"(src));
}
#define CP_COMMIT() asm volatile("cp.async.commit_group;")
#define CP_WAIT1() asm volatile("cp.async.wait_group 1;")
__device__ __forceinline__ void ldsm4(uint32_t* r, uint32_t a) {
    asm volatile("ldmatrix.sync.aligned.m8n8.x4.shared.b16 {%0,%1,%2,%3}, [%4];"
                 : "=r"(r[0]), "=r"(r[1]), "=r"(r[2]), "=r"(r[3]) : "r"(a));
}
__device__ __forceinline__ void ldsm4t(uint32_t* r, uint32_t a) {
    asm volatile("ldmatrix.sync.aligned.m8n8.x4.trans.shared.b16 {%0,%1,%2,%3}, [%4];"
                 : "=r"(r[0]), "=r"(r[1]), "=r"(r[2]), "=r"(r[3]) : "r"(a));
}
__device__ __forceinline__ void mma16816h(float* d, const uint32_t* a, uint32_t b0, uint32_t b1) {
    asm volatile(
        "mma.sync.aligned.m16n8k16.row.col.f32.f16.f16.f32 "
        "{%0,%1,%2,%3},{%4,%5,%6,%7},{%8,%9},{%0,%1,%2,%3};"
        : "+f"(d[0]), "+f"(d[1]), "+f"(d[2]), "+f"(d[3])
        : "r"(a[0]), "r"(a[1]), "r"(a[2]), "r"(a[3]), "r"(b0), "r"(b1));
}
__device__ __forceinline__ uint32_t off128(int r, int u) {
    return (uint32_t)(r * 128 + ((u ^ (r & 7)) << 4));
}
__device__ __forceinline__ uint32_t off256(int r, int u) {
    return (uint32_t)(r * 256 + ((((u ^ r) & 7) | (u & 8)) << 4));
}

// ---------------- fused weight convert: w1, w3, w2 -> fp16 ----------------
#define SEG_ (2097152u)   // float4 count per tensor
__global__ void wconvert_kernel(const float* __restrict__ w1, const float* __restrict__ w3,
                                const float* __restrict__ w2) {
    uint32_t idx = blockIdx.x * 256 + threadIdx.x;
    uint32_t seg = idx / SEG_, off = idx % SEG_;
    const float* src = (seg == 0) ? w1 : (seg == 1) ? w3 : w2;
    uint16_t* dst = (seg == 0) ? g_w1f : (seg == 1) ? g_w3f : g_w2f;
    float4 v = ((const float4*)src)[off];
    ((uint2*)dst)[off] = make_uint2(cvt1h(v.x, v.y), cvt1h(v.z, v.w));
}

// ---------------- prep ----------------
__global__ void prep_kernel(const unsigned char* __restrict__ pad,
                            const unsigned char* __restrict__ mid) {
    __shared__ int onebyte;
    __shared__ int cnts[B_];
    int tid = threadIdx.x;
    if (tid == 0) onebyte = 0;
    if (tid < B_) cnts[tid] = 0;
    if (tid < E_) g_cnt[tid] = 0;
    __syncthreads();
    int found = 0;
    for (int i = tid; i < 2048; i += 256)
        if (pad[4 * i + 1]) found = 1;
    if (found) onebyte = 1;
    __syncthreads();
    bool b1 = (onebyte != 0);
    const unsigned int* pw = (const unsigned int*)pad;
    const unsigned int* mw = (const unsigned int*)mid;
    for (int t = tid; t < T_; t += 256) {
        bool p = b1 ? (pad[t] != 0) : (pw[t] != 0);
        bool m = b1 ? (mid[t] != 0) : (mw[t] != 0);
        unsigned char np = (!p && !m) ? 1 : 0;
        g_nonpad[t] = np;
        if (np) atomicAdd(&cnts[t >> 11], 1);
    }
    for (int i = tid; i < E_ * B_ * D_; i += 256) g_mean[i] = 0.f;
    __syncthreads();
    if (tid < B_) g_invcnt[tid] = 1.f / (float)cnts[tid];
}

// ---------------- gating + x fp16 conversion (fused) ----------------
__global__ void xgate_kernel(const float* __restrict__ x,
                             const float* __restrict__ gw,
                             float* __restrict__ route_out) {
    int warp = threadIdx.x >> 5, lane = threadIdx.x & 31;
    int t = blockIdx.x * 8 + warp;
    const float* xr = x + (size_t)t * D_;
    float acc[8];
#pragma unroll
    for (int e = 0; e < 8; e++) acc[e] = 0.f;
    for (int d = lane; d < D_; d += 32) {
        float xv = xr[d];
        float4 g0 = *(const float4*)(gw + (size_t)d * 8);
        float4 g1 = *(const float4*)(gw + (size_t)d * 8 + 4);
        acc[0] += xv * g0.x; acc[1] += xv * g0.y;
        acc[2] += xv * g0.z; acc[3] += xv * g0.w;
        acc[4] += xv * g1.x; acc[5] += xv * g1.y;
        acc[6] += xv * g1.z; acc[7] += xv * g1.w;
    }
#pragma unroll
    for (int o = 16; o; o >>= 1)
#pragma unroll
        for (int e = 0; e < 8; e++)
            acc[e] += __shfl_xor_sync(0xffffffffu, acc[e], o);
    if (lane == 0) {
        float mx = acc[0];
#pragma unroll
        for (int e = 1; e < 8; e++) mx = fmaxf(mx, acc[e]);
        float p[8], s = 0.f;
#pragma unroll
        for (int e = 0; e < 8; e++) { p[e] = __expf(acc[e] - mx); s += p[e]; }
        float inv = 1.f / s;
#pragma unroll
        for (int e = 0; e < 8; e++) p[e] *= inv;
        float* ro = route_out + (size_t)t * 8;
#pragma unroll
        for (int e = 0; e < 8; e++) ro[e] = p[e];
        int e0 = 0;
#pragma unroll
        for (int e = 1; e < 8; e++) if (p[e] > p[e0]) e0 = e;
        int e1 = (e0 == 0) ? 1 : 0;
#pragma unroll
        for (int e = 0; e < 8; e++) if (e != e0 && p[e] > p[e1]) e1 = e;
        float inv2 = 1.f / (p[e0] + p[e1]);
        int s0 = atomicAdd(&g_cnt[e0], 1);
        g_btok[e0 * T_ + s0] = t; g_bwt[e0 * T_ + s0] = p[e0] * inv2;
        int s1 = atomicAdd(&g_cnt[e1], 1);
        g_btok[e1 * T_ + s1] = t; g_bwt[e1 * T_ + s1] = p[e1] * inv2;
    }
    // convert this block's 8 token rows to fp16 (reads L1/L2-hot)
    size_t base4 = (size_t)blockIdx.x * 2048;
#pragma unroll
    for (int k = 0; k < 8; k++) {
        size_t i = base4 + threadIdx.x + k * 256;
        float4 v = ((const float4*)x)[i];
        ((uint2*)g_xf)[i] = make_uint2(cvt1h(v.x, v.y), cvt1h(v.z, v.w));
    }
}

__global__ void scan_kernel() {
    if (threadIdx.x == 0) {
        int acc = 0;
        for (int e = 0; e < E_; e++) { g_base[e] = acc; acc += g_cnt[e]; }
    }
}

// ============ ffn1: hact = silu(X@w1)*(X@w3), fp16, BK=64, 3-stage, 2 CTAs/SM ============
__global__ __launch_bounds__(256, 2) void ffn1_mma(int dummy) {
    extern __shared__ char dyn[];
    __shared__ int toks[BM];
    int e = blockIdx.y >> 6, mt = blockIdx.y & 63;
    int cnt = g_cnt[e];
    int row0 = mt * BM;
    if (row0 >= cnt) return;
    int rows = min(BM, cnt - row0);
    int n0 = blockIdx.x * 64;
    int tid = threadIdx.x, wid = tid >> 5, lane = tid & 31;
    if (tid < BM)
        toks[tid] = (tid < rows) ? g_btok[e * T_ + row0 + tid] : g_btok[e * T_ + row0];
    __syncthreads();
    uint32_t sb = (smem_u32(dyn) + 1023u) & ~1023u;

    int am = tid >> 1, ub = (tid & 1) * 4;
    const uint16_t* pA = g_xf + (size_t)toks[am] * D_ + (tid & 1) * 32;
    uint32_t dA[4] = { off128(am, ub), off128(am, ub + 1), off128(am, ub + 2), off128(am, ub + 3) };
    int bk = tid >> 2, bu = (tid & 3) * 2;
    size_t woff = ((size_t)e * D_ + bk) * H_ + n0 + bu * 8;
    const uint16_t* p1 = g_w1f + woff;
    const uint16_t* p3 = g_w3f + woff;
    uint32_t dB0 = off128(bk, bu), dB1 = off128(bk, bu + 1);

    auto issue = [&](int c) {
        uint32_t st = sb + (uint32_t)(c % 3) * SSZ;
        const uint16_t* a = pA + c * 64;
#pragma unroll
        for (int j = 0; j < 4; j++) cpa16(st + dA[j], a + j * 8);
        size_t wo = (size_t)c * 64 * H_;
        cpa16(st + 16384u + dB0, p1 + wo);
        cpa16(st + 16384u + dB1, p1 + wo + 8);
        cpa16(st + 24576u + dB0, p3 + wo);
        cpa16(st + 24576u + dB1, p3 + wo + 8);
        CP_COMMIT();
    };

    float acc1[2][4][4], acc3[2][4][4];
#pragma unroll
    for (int a = 0; a < 2; a++)
#pragma unroll
        for (int b = 0; b < 4; b++)
#pragma unroll
            for (int q = 0; q < 4; q++) { acc1[a][b][q] = 0.f; acc3[a][b][q] = 0.f; }

    int lr = (lane & 7) + ((lane >> 3) & 1) * 8;
    int uo = (lane >> 4) & 1;
    int mq = wid & 3, nh = wid >> 2;

    issue(0); issue(1);
    for (int c = 0; c < NCH; c++) {
        CP_WAIT1();
        __syncthreads();
        if (c + 2 < NCH) issue(c + 2); else CP_COMMIT();
        uint32_t base = sb + (uint32_t)(c % 3) * SSZ;
        uint32_t aT = base, w1T = base + 16384u, w3T = base + 24576u;
#pragma unroll
        for (int kb = 0; kb < 4; kb++) {
            uint32_t A[2][4];
#pragma unroll
            for (int mb = 0; mb < 2; mb++)
                ldsm4(A[mb], aT + off128(mq * 32 + mb * 16 + lr, kb * 2 + uo));
            int krow = kb * 16 + lr;
#pragma unroll
            for (int nb = 0; nb < 2; nb++) {
                uint32_t so = off128(krow, nh * 4 + nb * 2 + uo);
                uint32_t F[4];
                ldsm4t(F, w1T + so);
#pragma unroll
                for (int mb = 0; mb < 2; mb++) {
                    mma16816h(acc1[mb][nb * 2 + 0], A[mb], F[0], F[1]);
                    mma16816h(acc1[mb][nb * 2 + 1], A[mb], F[2], F[3]);
                }
                ldsm4t(F, w3T + so);
#pragma unroll
                for (int mb = 0; mb < 2; mb++) {
                    mma16816h(acc3[mb][nb * 2 + 0], A[mb], F[0], F[1]);
                    mma16816h(acc3[mb][nb * 2 + 1], A[mb], F[2], F[3]);
                }
            }
        }
    }
    int gbase = g_base[e] + row0;
    int r0c = lane >> 2, cc = 2 * (lane & 3);
#pragma unroll
    for (int mb = 0; mb < 2; mb++)
#pragma unroll
        for (int nf = 0; nf < 4; nf++) {
            int col = n0 + nh * 32 + nf * 8 + cc;
#pragma unroll
            for (int hrow = 0; hrow < 2; hrow++) {
                int m0 = mq * 32 + mb * 16 + r0c + hrow * 8;
                if (m0 < rows) {
                    float a0 = acc1[mb][nf][hrow * 2],     b0 = acc3[mb][nf][hrow * 2];
                    float a1 = acc1[mb][nf][hrow * 2 + 1], b1 = acc3[mb][nf][hrow * 2 + 1];
                    float o0 = a0 / (1.f + __expf(-a0)) * b0;
                    float o1 = a1 / (1.f + __expf(-a1)) * b1;
                    size_t off = ((size_t)(gbase + m0) * H_ + col) >> 1;
                    ((uint32_t*)g_hactf)[off] = cvt1h(o0, o1);
                }
            }
        }
}

// ============ ffn2: Y = hact @ w2, fp16, BK=64, 3-stage, 2 CTAs/SM, scatter ============
__global__ __launch_bounds__(256, 2) void ffn2_mma(float* __restrict__ outF) {
    extern __shared__ char dyn[];
    __shared__ int toks[BM];
    __shared__ float wts[BM];
    int e = blockIdx.y >> 6, mt = blockIdx.y & 63;
    int cnt = g_cnt[e];
    int row0 = mt * BM;
    if (row0 >= cnt) return;
    int rows = min(BM, cnt - row0);
    int n0 = blockIdx.x * 128;
    int tid = threadIdx.x, wid = tid >> 5, lane = tid & 31;
    if (tid < BM) {
        int idx = e * T_ + row0 + tid;
        toks[tid] = (tid < rows) ? g_btok[idx] : 0;
        wts[tid] = (tid < rows) ? g_bwt[idx] : 0.f;
    }
    __syncthreads();
    uint32_t sb = (smem_u32(dyn) + 1023u) & ~1023u;
    int gbase = g_base[e] + row0;

    int am = tid >> 1, ub = (tid & 1) * 4;
    const uint16_t* pA = g_hactf + (size_t)(gbase + min(am, rows - 1)) * H_ + (tid & 1) * 32;
    uint32_t dA[4] = { off128(am, ub), off128(am, ub + 1), off128(am, ub + 2), off128(am, ub + 3) };
    int bk = tid >> 2, bu4 = (tid & 3) * 4;
    size_t woff = ((size_t)e * H_ + bk) * D_ + n0 + bu4 * 8;
    const uint16_t* p2 = g_w2f + woff;
    uint32_t dB[4] = { off256(bk, bu4), off256(bk, bu4 + 1), off256(bk, bu4 + 2), off256(bk, bu4 + 3) };

    auto issue = [&](int c) {
        uint32_t st = sb + (uint32_t)(c % 3) * SSZ;
        const uint16_t* a = pA + c * 64;
#pragma unroll
        for (int j = 0; j < 4; j++) cpa16(st + dA[j], a + j * 8);
        size_t wo = (size_t)c * 64 * D_;
#pragma unroll
        for (int j = 0; j < 4; j++) cpa16(st + 16384u + dB[j], p2 + wo + j * 8);
        CP_COMMIT();
    };

    float acc[2][8][4];
#pragma unroll
    for (int a = 0; a < 2; a++)
#pragma unroll
        for (int b = 0; b < 8; b++)
#pragma unroll
            for (int q = 0; q < 4; q++) acc[a][b][q] = 0.f;

    int lr = (lane & 7) + ((lane >> 3) & 1) * 8;
    int uo = (lane >> 4) & 1;
    int mq = wid & 3, nh = wid >> 2;

    issue(0); issue(1);
    for (int c = 0; c < NCH; c++) {
        CP_WAIT1();
        __syncthreads();
        if (c + 2 < NCH) issue(c + 2); else CP_COMMIT();
        uint32_t base = sb + (uint32_t)(c % 3) * SSZ;
        uint32_t aT = base, w2T = base + 16384u;
#pragma unroll
        for (int kb = 0; kb < 4; kb++) {
            uint32_t A[2][4];
#pragma unroll
            for (int mb = 0; mb < 2; mb++)
                ldsm4(A[mb], aT + off128(mq * 32 + mb * 16 + lr, kb * 2 + uo));
            int krow = kb * 16 + lr;
#pragma unroll
            for (int nb = 0; nb < 4; nb++) {
                uint32_t F[4];
                ldsm4t(F, w2T + off256(krow, nh * 8 + nb * 2 + uo));
#pragma unroll
                for (int mb = 0; mb < 2; mb++) {
                    mma16816h(acc[mb][nb * 2 + 0], A[mb], F[0], F[1]);
                    mma16816h(acc[mb][nb * 2 + 1], A[mb], F[2], F[3]);
                }
            }
        }
    }
    int r0c = lane >> 2, cc = 2 * (lane & 3);
#pragma unroll
    for (int mb = 0; mb < 2; mb++)
#pragma unroll
        for (int nf = 0; nf < 8; nf++) {
            int col = n0 + nh * 64 + nf * 8 + cc;
#pragma unroll
            for (int hrow = 0; hrow < 2; hrow++) {
                int m0 = mq * 32 + mb * 16 + r0c + hrow * 8;
                if (m0 < rows) {
                    int t = toks[m0];
                    float wt = wts[m0];
                    float v0 = wt * acc[mb][nf][hrow * 2];
                    float v1 = wt * acc[mb][nf][hrow * 2 + 1];
                    float* fo = outF + (size_t)t * D_ + col;
                    atomicAdd(fo, v0);
                    atomicAdd(fo + 1, v1);
                    if (g_nonpad[t]) {
                        float* mp = g_mean + (size_t)(e * B_ + (t >> 11)) * D_ + col;
                        atomicAdd(mp, v0);
                        atomicAdd(mp + 1, v1);
                    }
                }
            }
        }
}

// ---------------- classifier ----------------
__global__ void clf_kernel(const float* __restrict__ clf_w,
                           const float* __restrict__ clf_b,
                           float* __restrict__ outL) {
    __shared__ float dots[32];
    int w = threadIdx.x >> 5, lane = threadIdx.x & 31;
    const float* m = g_mean + (size_t)w * D_;
    float s = 0.f;
    for (int d = lane; d < D_; d += 32) s += m[d] * clf_w[d];
#pragma unroll
    for (int o = 16; o; o >>= 1) s += __shfl_xor_sync(0xffffffffu, s, o);
    if (lane == 0) dots[w] = s;
    __syncthreads();
    if (threadIdx.x < 32) {
        int e = threadIdx.x >> 2, b = threadIdx.x & 3;
        float c = 0.f;
        for (int ee = 0; ee <= e; ee++) c += dots[ee * 4 + b];
        outL[e * B_ + b] = c * g_invcnt[b] + clf_b[0];
    }
}

// ---------------- launch ----------------
extern "C" void kernel_launch(void* const* d_in, const int* in_sizes, int n_in,
                              void* d_out, int out_size) {
    int base = 4;
    if (n_in == 9 || (n_in > 3 && in_sizes[3] != 1)) base = 3;
    const float* x = (const float*)d_in[0];
    const unsigned char* pad = (const unsigned char*)d_in[1];
    const unsigned char* mid = (const unsigned char*)d_in[2];
    const float* gw = (const float*)d_in[base + 0];
    const float* w1 = (const float*)d_in[base + 1];
    const float* w2 = (const float*)d_in[base + 2];
    const float* w3 = (const float*)d_in[base + 3];
    const float* cw = (const float*)d_in[base + 4];
    const float* cb = (const float*)d_in[base + 5];
    float* out = (float*)d_out;

    float* out_final = out;
    float* out_logits = out + (size_t)T_ * D_;
    float* out_route = out + (size_t)T_ * D_ + E_ * B_;

    const int smem = 3 * (int)SSZ + 1024;   // 99328 -> 2 CTAs/SM
    cudaFuncSetAttribute(ffn1_mma, cudaFuncAttributeMaxDynamicSharedMemorySize, smem);
    cudaFuncSetAttribute(ffn2_mma, cudaFuncAttributeMaxDynamicSharedMemorySize, smem);

    cudaMemsetAsync(out_final, 0, (size_t)T_ * D_ * sizeof(float), 0);
    wconvert_kernel<<<3 * 8192, 256>>>(w1, w3, w2);
    prep_kernel<<<1, 256>>>(pad, mid);
    xgate_kernel<<<T_ / 8, 256>>>(x, gw, out_route);
    scan_kernel<<<1, 32>>>();
    ffn1_mma<<<dim3(H_ / 64, E_ * 64), 256, smem>>>(0);
    ffn2_mma<<<dim3(D_ / 128, E_ * 64), 256, smem>>>(out_final);
    clf_kernel<<<1, 1024>>>(cw, cb, out_logits);
}

// round 15
// speedup vs baseline: 1.2490x; 1.0540x over previous
#include <cuda_runtime.h>
#include <cuda_fp16.h>
#include <cstdint>

#define T_ 8192
#define D_ 1024
#define H_ 1024
#define E_ 8
#define B_ 4
#define S_ 2048

#define BM 128
#define SSZ 32768u    // stage: A 16KB + B 16KB (BK=64)
#define NCH 16        // 1024 / 64

// ---------------- scratch (no allocation allowed) ----------------
__device__ int g_cnt[E_];
__device__ int g_base[E_];
__device__ int g_btok[E_ * T_];
__device__ float g_bwt[E_ * T_];
__device__ unsigned char g_nonpad[T_];
__device__ float g_invcnt[B_];
__device__ float g_dote[E_ * B_];     // per-(expert,batch) partial dot(mean-sum, clf_w)
// fp16 scratch
__device__ uint16_t g_xf[(size_t)T_ * D_];
__device__ uint16_t g_w1f[(size_t)E_ * D_ * H_];
__device__ uint16_t g_w3f[(size_t)E_ * D_ * H_];
__device__ uint16_t g_w2f[(size_t)E_ * H_ * D_];
__device__ uint16_t g_hactf[(size_t)2 * T_ * H_];

// ================= helpers =================
__device__ __forceinline__ uint32_t smem_u32(const void* p) {
    uint32_t a;
    asm("{ .reg .u64 t; cvta.to.shared.u64 t, %1; cvt.u32.u64 %0, t; }" : "=r"(a) : "l"(p));
    return a;
}
__device__ __forceinline__ uint32_t cvt1h(float f0, float f1) {
    uint32_t h;
    asm("cvt.rn.f16x2.f32 %0, %1, %2;" : "=r"(h) : "f"(f1), "f"(f0));
    return h;
}
__device__ __forceinline__ void cpa16(uint32_t dst, const void* src) {
    asm volatile("cp.async.cg.shared.global [%0], [%1], 16;" :: "r"(dst), "l"(src));
}
#define CP_COMMIT() asm volatile("cp.async.commit_group;")
#define CP_WAIT1() asm volatile("cp.async.wait_group 1;")
__device__ __forceinline__ void ldsm4(uint32_t* r, uint32_t a) {
    asm volatile("ldmatrix.sync.aligned.m8n8.x4.shared.b16 {%0,%1,%2,%3}, [%4];"
                 : "=r"(r[0]), "=r"(r[1]), "=r"(r[2]), "=r"(r[3]) : "r"(a));
}
__device__ __forceinline__ void ldsm4t(uint32_t* r, uint32_t a) {
    asm volatile("ldmatrix.sync.aligned.m8n8.x4.trans.shared.b16 {%0,%1,%2,%3}, [%4];"
                 : "=r"(r[0]), "=r"(r[1]), "=r"(r[2]), "=r"(r[3]) : "r"(a));
}
__device__ __forceinline__ void mma16816h(float* d, const uint32_t* a, uint32_t b0, uint32_t b1) {
    asm volatile(
        "mma.sync.aligned.m16n8k16.row.col.f32.f16.f16.f32 "
        "{%0,%1,%2,%3},{%4,%5,%6,%7},{%8,%9},{%0,%1,%2,%3};"
        : "+f"(d[0]), "+f"(d[1]), "+f"(d[2]), "+f"(d[3])
        : "r"(a[0]), "r"(a[1]), "r"(a[2]), "r"(a[3]), "r"(b0), "r"(b1));
}
__device__ __forceinline__ uint32_t off128(int r, int u) {
    return (uint32_t)(r * 128 + ((u ^ (r & 7)) << 4));
}
__device__ __forceinline__ uint32_t off256(int r, int u) {
    return (uint32_t)(r * 256 + ((((u ^ r) & 7) | (u & 8)) << 4));
}

// ---------------- fused weight convert: coalesced ILP x4 ----------------
#define SEG_ (2097152u)   // float4 count per tensor
__global__ void wconvert_kernel(const float* __restrict__ w1, const float* __restrict__ w3,
                                const float* __restrict__ w2) {
    uint32_t base = blockIdx.x * 1024 + threadIdx.x;
#pragma unroll
    for (int k = 0; k < 4; k++) {
        uint32_t idx = base + k * 256;
        uint32_t seg = idx / SEG_, off = idx % SEG_;
        const float4* s = (const float4*)((seg == 0) ? w1 : (seg == 1) ? w3 : w2);
        uint2* d = (uint2*)((seg == 0) ? g_w1f : (seg == 1) ? g_w3f : g_w2f);
        float4 v = s[off];
        d[off] = make_uint2(cvt1h(v.x, v.y), cvt1h(v.z, v.w));
    }
}

// ---------------- prep ----------------
__global__ void prep_kernel(const unsigned char* __restrict__ pad,
                            const unsigned char* __restrict__ mid) {
    __shared__ int onebyte;
    __shared__ int cnts[B_];
    int tid = threadIdx.x;
    if (tid == 0) onebyte = 0;
    if (tid < B_) cnts[tid] = 0;
    if (tid < E_) g_cnt[tid] = 0;
    if (tid < E_ * B_) g_dote[tid] = 0.f;
    __syncthreads();
    int found = 0;
    for (int i = tid; i < 2048; i += 256)
        if (pad[4 * i + 1]) found = 1;
    if (found) onebyte = 1;
    __syncthreads();
    bool b1 = (onebyte != 0);
    const unsigned int* pw = (const unsigned int*)pad;
    const unsigned int* mw = (const unsigned int*)mid;
    for (int t = tid; t < T_; t += 256) {
        bool p = b1 ? (pad[t] != 0) : (pw[t] != 0);
        bool m = b1 ? (mid[t] != 0) : (mw[t] != 0);
        unsigned char np = (!p && !m) ? 1 : 0;
        g_nonpad[t] = np;
        if (np) atomicAdd(&cnts[t >> 11], 1);
    }
    __syncthreads();
    if (tid < B_) g_invcnt[tid] = 1.f / (float)cnts[tid];
}

// ---------------- gating + x fp16 conversion (fused) ----------------
__global__ void xgate_kernel(const float* __restrict__ x,
                             const float* __restrict__ gw,
                             float* __restrict__ route_out) {
    int warp = threadIdx.x >> 5, lane = threadIdx.x & 31;
    int t = blockIdx.x * 8 + warp;
    const float* xr = x + (size_t)t * D_;
    float acc[8];
#pragma unroll
    for (int e = 0; e < 8; e++) acc[e] = 0.f;
    for (int d = lane; d < D_; d += 32) {
        float xv = xr[d];
        float4 g0 = *(const float4*)(gw + (size_t)d * 8);
        float4 g1 = *(const float4*)(gw + (size_t)d * 8 + 4);
        acc[0] += xv * g0.x; acc[1] += xv * g0.y;
        acc[2] += xv * g0.z; acc[3] += xv * g0.w;
        acc[4] += xv * g1.x; acc[5] += xv * g1.y;
        acc[6] += xv * g1.z; acc[7] += xv * g1.w;
    }
#pragma unroll
    for (int o = 16; o; o >>= 1)
#pragma unroll
        for (int e = 0; e < 8; e++)
            acc[e] += __shfl_xor_sync(0xffffffffu, acc[e], o);
    if (lane == 0) {
        float mx = acc[0];
#pragma unroll
        for (int e = 1; e < 8; e++) mx = fmaxf(mx, acc[e]);
        float p[8], s = 0.f;
#pragma unroll
        for (int e = 0; e < 8; e++) { p[e] = __expf(acc[e] - mx); s += p[e]; }
        float inv = 1.f / s;
#pragma unroll
        for (int e = 0; e < 8; e++) p[e] *= inv;
        float* ro = route_out + (size_t)t * 8;
#pragma unroll
        for (int e = 0; e < 8; e++) ro[e] = p[e];
        int e0 = 0;
#pragma unroll
        for (int e = 1; e < 8; e++) if (p[e] > p[e0]) e0 = e;
        int e1 = (e0 == 0) ? 1 : 0;
#pragma unroll
        for (int e = 0; e < 8; e++) if (e != e0 && p[e] > p[e1]) e1 = e;
        float inv2 = 1.f / (p[e0] + p[e1]);
        int s0 = atomicAdd(&g_cnt[e0], 1);
        g_btok[e0 * T_ + s0] = t; g_bwt[e0 * T_ + s0] = p[e0] * inv2;
        int s1 = atomicAdd(&g_cnt[e1], 1);
        g_btok[e1 * T_ + s1] = t; g_bwt[e1 * T_ + s1] = p[e1] * inv2;
    }
    // convert this block's 8 token rows to fp16 (reads L1/L2-hot)
    size_t base4 = (size_t)blockIdx.x * 2048;
#pragma unroll
    for (int k = 0; k < 8; k++) {
        size_t i = base4 + threadIdx.x + k * 256;
        float4 v = ((const float4*)x)[i];
        ((uint2*)g_xf)[i] = make_uint2(cvt1h(v.x, v.y), cvt1h(v.z, v.w));
    }
}

__global__ void scan_kernel() {
    if (threadIdx.x == 0) {
        int acc = 0;
        for (int e = 0; e < E_; e++) { g_base[e] = acc; acc += g_cnt[e]; }
    }
}

// ============ ffn1: hact = silu(X@w1)*(X@w3), fp16, BK=64, 3-stage, 2 CTAs/SM ============
__global__ __launch_bounds__(256, 2) void ffn1_mma(int dummy) {
    extern __shared__ char dyn[];
    __shared__ int toks[BM];
    int e = blockIdx.y >> 6, mt = blockIdx.y & 63;
    int cnt = g_cnt[e];
    int row0 = mt * BM;
    if (row0 >= cnt) return;
    int rows = min(BM, cnt - row0);
    int n0 = blockIdx.x * 64;
    int tid = threadIdx.x, wid = tid >> 5, lane = tid & 31;
    if (tid < BM)
        toks[tid] = (tid < rows) ? g_btok[e * T_ + row0 + tid] : g_btok[e * T_ + row0];
    __syncthreads();
    uint32_t sb = (smem_u32(dyn) + 1023u) & ~1023u;

    int am = tid >> 1, ub = (tid & 1) * 4;
    const uint16_t* pA = g_xf + (size_t)toks[am] * D_ + (tid & 1) * 32;
    uint32_t dA[4] = { off128(am, ub), off128(am, ub + 1), off128(am, ub + 2), off128(am, ub + 3) };
    int bk = tid >> 2, bu = (tid & 3) * 2;
    size_t woff = ((size_t)e * D_ + bk) * H_ + n0 + bu * 8;
    const uint16_t* p1 = g_w1f + woff;
    const uint16_t* p3 = g_w3f + woff;
    uint32_t dB0 = off128(bk, bu), dB1 = off128(bk, bu + 1);

    auto issue = [&](int c) {
        uint32_t st = sb + (uint32_t)(c % 3) * SSZ;
        const uint16_t* a = pA + c * 64;
#pragma unroll
        for (int j = 0; j < 4; j++) cpa16(st + dA[j], a + j * 8);
        size_t wo = (size_t)c * 64 * H_;
        cpa16(st + 16384u + dB0, p1 + wo);
        cpa16(st + 16384u + dB1, p1 + wo + 8);
        cpa16(st + 24576u + dB0, p3 + wo);
        cpa16(st + 24576u + dB1, p3 + wo + 8);
        CP_COMMIT();
    };

    float acc1[2][4][4], acc3[2][4][4];
#pragma unroll
    for (int a = 0; a < 2; a++)
#pragma unroll
        for (int b = 0; b < 4; b++)
#pragma unroll
            for (int q = 0; q < 4; q++) { acc1[a][b][q] = 0.f; acc3[a][b][q] = 0.f; }

    int lr = (lane & 7) + ((lane >> 3) & 1) * 8;
    int uo = (lane >> 4) & 1;
    int mq = wid & 3, nh = wid >> 2;

    issue(0); issue(1);
    for (int c = 0; c < NCH; c++) {
        CP_WAIT1();
        __syncthreads();
        if (c + 2 < NCH) issue(c + 2); else CP_COMMIT();
        uint32_t base = sb + (uint32_t)(c % 3) * SSZ;
        uint32_t aT = base, w1T = base + 16384u, w3T = base + 24576u;
#pragma unroll
        for (int kb = 0; kb < 4; kb++) {
            uint32_t A[2][4];
#pragma unroll
            for (int mb = 0; mb < 2; mb++)
                ldsm4(A[mb], aT + off128(mq * 32 + mb * 16 + lr, kb * 2 + uo));
            int krow = kb * 16 + lr;
#pragma unroll
            for (int nb = 0; nb < 2; nb++) {
                uint32_t so = off128(krow, nh * 4 + nb * 2 + uo);
                uint32_t F[4];
                ldsm4t(F, w1T + so);
#pragma unroll
                for (int mb = 0; mb < 2; mb++) {
                    mma16816h(acc1[mb][nb * 2 + 0], A[mb], F[0], F[1]);
                    mma16816h(acc1[mb][nb * 2 + 1], A[mb], F[2], F[3]);
                }
                ldsm4t(F, w3T + so);
#pragma unroll
                for (int mb = 0; mb < 2; mb++) {
                    mma16816h(acc3[mb][nb * 2 + 0], A[mb], F[0], F[1]);
                    mma16816h(acc3[mb][nb * 2 + 1], A[mb], F[2], F[3]);
                }
            }
        }
    }
    int gbase = g_base[e] + row0;
    int r0c = lane >> 2, cc = 2 * (lane & 3);
#pragma unroll
    for (int mb = 0; mb < 2; mb++)
#pragma unroll
        for (int nf = 0; nf < 4; nf++) {
            int col = n0 + nh * 32 + nf * 8 + cc;
#pragma unroll
            for (int hrow = 0; hrow < 2; hrow++) {
                int m0 = mq * 32 + mb * 16 + r0c + hrow * 8;
                if (m0 < rows) {
                    float a0 = acc1[mb][nf][hrow * 2],     b0 = acc3[mb][nf][hrow * 2];
                    float a1 = acc1[mb][nf][hrow * 2 + 1], b1 = acc3[mb][nf][hrow * 2 + 1];
                    float o0 = a0 / (1.f + __expf(-a0)) * b0;
                    float o1 = a1 / (1.f + __expf(-a1)) * b1;
                    size_t off = ((size_t)(gbase + m0) * H_ + col) >> 1;
                    ((uint32_t*)g_hactf)[off] = cvt1h(o0, o1);
                }
            }
        }
}

// ============ ffn2: Y = hact @ w2, fp16, BK=64, 3-stage, 2 CTAs/SM, scatter ============
// Mean path replaced by scalar dot-products with clf_w: register accumulate ->
// warp reduce -> smem -> 4 global atomics per CTA (vs 11.7M contended atomics).
__global__ __launch_bounds__(256, 2) void ffn2_mma(float* __restrict__ outF,
                                                   const float* __restrict__ clf_w) {
    extern __shared__ char dyn[];
    __shared__ int toks[BM];
    __shared__ float wts[BM];
    __shared__ float sdot[B_];
    int e = blockIdx.y >> 6, mt = blockIdx.y & 63;
    int cnt = g_cnt[e];
    int row0 = mt * BM;
    if (row0 >= cnt) return;
    int rows = min(BM, cnt - row0);
    int n0 = blockIdx.x * 128;
    int tid = threadIdx.x, wid = tid >> 5, lane = tid & 31;
    if (tid < BM) {
        int idx = e * T_ + row0 + tid;
        toks[tid] = (tid < rows) ? g_btok[idx] : 0;
        wts[tid] = (tid < rows) ? g_bwt[idx] : 0.f;
    }
    if (tid < B_) sdot[tid] = 0.f;
    __syncthreads();
    uint32_t sb = (smem_u32(dyn) + 1023u) & ~1023u;
    int gbase = g_base[e] + row0;

    int am = tid >> 1, ub = (tid & 1) * 4;
    const uint16_t* pA = g_hactf + (size_t)(gbase + min(am, rows - 1)) * H_ + (tid & 1) * 32;
    uint32_t dA[4] = { off128(am, ub), off128(am, ub + 1), off128(am, ub + 2), off128(am, ub + 3) };
    int bk = tid >> 2, bu4 = (tid & 3) * 4;
    size_t woff = ((size_t)e * H_ + bk) * D_ + n0 + bu4 * 8;
    const uint16_t* p2 = g_w2f + woff;
    uint32_t dB[4] = { off256(bk, bu4), off256(bk, bu4 + 1), off256(bk, bu4 + 2), off256(bk, bu4 + 3) };

    auto issue = [&](int c) {
        uint32_t st = sb + (uint32_t)(c % 3) * SSZ;
        const uint16_t* a = pA + c * 64;
#pragma unroll
        for (int j = 0; j < 4; j++) cpa16(st + dA[j], a + j * 8);
        size_t wo = (size_t)c * 64 * D_;
#pragma unroll
        for (int j = 0; j < 4; j++) cpa16(st + 16384u + dB[j], p2 + wo + j * 8);
        CP_COMMIT();
    };

    float acc[2][8][4];
#pragma unroll
    for (int a = 0; a < 2; a++)
#pragma unroll
        for (int b = 0; b < 8; b++)
#pragma unroll
            for (int q = 0; q < 4; q++) acc[a][b][q] = 0.f;

    int lr = (lane & 7) + ((lane >> 3) & 1) * 8;
    int uo = (lane >> 4) & 1;
    int mq = wid & 3, nh = wid >> 2;

    issue(0); issue(1);
    for (int c = 0; c < NCH; c++) {
        CP_WAIT1();
        __syncthreads();
        if (c + 2 < NCH) issue(c + 2); else CP_COMMIT();
        uint32_t base = sb + (uint32_t)(c % 3) * SSZ;
        uint32_t aT = base, w2T = base + 16384u;
#pragma unroll
        for (int kb = 0; kb < 4; kb++) {
            uint32_t A[2][4];
#pragma unroll
            for (int mb = 0; mb < 2; mb++)
                ldsm4(A[mb], aT + off128(mq * 32 + mb * 16 + lr, kb * 2 + uo));
            int krow = kb * 16 + lr;
#pragma unroll
            for (int nb = 0; nb < 4; nb++) {
                uint32_t F[4];
                ldsm4t(F, w2T + off256(krow, nh * 8 + nb * 2 + uo));
#pragma unroll
                for (int mb = 0; mb < 2; mb++) {
                    mma16816h(acc[mb][nb * 2 + 0], A[mb], F[0], F[1]);
                    mma16816h(acc[mb][nb * 2 + 1], A[mb], F[2], F[3]);
                }
            }
        }
    }
    // epilogue: scale, scatter to outF, accumulate clf dot partials per batch
    int r0c = lane >> 2, cc = 2 * (lane & 3);
    float db0 = 0.f, db1 = 0.f, db2 = 0.f, db3 = 0.f;
#pragma unroll
    for (int mb = 0; mb < 2; mb++)
#pragma unroll
        for (int nf = 0; nf < 8; nf++) {
            int col = n0 + nh * 64 + nf * 8 + cc;
            float cw0 = __ldg(clf_w + col);
            float cw1 = __ldg(clf_w + col + 1);
#pragma unroll
            for (int hrow = 0; hrow < 2; hrow++) {
                int m0 = mq * 32 + mb * 16 + r0c + hrow * 8;
                if (m0 < rows) {
                    int t = toks[m0];
                    float wt = wts[m0];
                    float v0 = wt * acc[mb][nf][hrow * 2];
                    float v1 = wt * acc[mb][nf][hrow * 2 + 1];
                    float* fo = outF + (size_t)t * D_ + col;
                    atomicAdd(fo, v0);
                    atomicAdd(fo + 1, v1);
                    if (g_nonpad[t]) {
                        float p = v0 * cw0 + v1 * cw1;
                        int bb = t >> 11;
                        db0 += (bb == 0) ? p : 0.f;
                        db1 += (bb == 1) ? p : 0.f;
                        db2 += (bb == 2) ? p : 0.f;
                        db3 += (bb == 3) ? p : 0.f;
                    }
                }
            }
        }
    // warp-reduce 4 batch partials, one smem add per warp, 4 global atomics per CTA
    float db[4] = { db0, db1, db2, db3 };
#pragma unroll
    for (int j = 0; j < 4; j++) {
        float v = db[j];
#pragma unroll
        for (int o = 16; o; o >>= 1) v += __shfl_xor_sync(0xffffffffu, v, o);
        if (lane == 0 && v != 0.f) atomicAdd(&sdot[j], v);
    }
    __syncthreads();
    if (tid < B_) {
        float v = sdot[tid];
        if (v != 0.f) atomicAdd(&g_dote[e * B_ + tid], v);
    }
}

// ---------------- classifier (now trivial: cumsum of precomputed dots) ----------------
__global__ void clf_kernel(const float* __restrict__ clf_b,
                           float* __restrict__ outL) {
    int tid = threadIdx.x;
    if (tid < E_ * B_) {
        int e = tid >> 2, b = tid & 3;
        float c = 0.f;
        for (int ee = 0; ee <= e; ee++) c += g_dote[ee * B_ + b];
        outL[e * B_ + b] = c * g_invcnt[b] + clf_b[0];
    }
}

// ---------------- launch ----------------
extern "C" void kernel_launch(void* const* d_in, const int* in_sizes, int n_in,
                              void* d_out, int out_size) {
    int base = 4;
    if (n_in == 9 || (n_in > 3 && in_sizes[3] != 1)) base = 3;
    const float* x = (const float*)d_in[0];
    const unsigned char* pad = (const unsigned char*)d_in[1];
    const unsigned char* mid = (const unsigned char*)d_in[2];
    const float* gw = (const float*)d_in[base + 0];
    const float* w1 = (const float*)d_in[base + 1];
    const float* w2 = (const float*)d_in[base + 2];
    const float* w3 = (const float*)d_in[base + 3];
    const float* cw = (const float*)d_in[base + 4];
    const float* cb = (const float*)d_in[base + 5];
    float* out = (float*)d_out;

    float* out_final = out;
    float* out_logits = out + (size_t)T_ * D_;
    float* out_route = out + (size_t)T_ * D_ + E_ * B_;

    const int smem = 3 * (int)SSZ + 1024;   // 99328 -> 2 CTAs/SM
    cudaFuncSetAttribute(ffn1_mma, cudaFuncAttributeMaxDynamicSharedMemorySize, smem);
    cudaFuncSetAttribute(ffn2_mma, cudaFuncAttributeMaxDynamicSharedMemorySize, smem);

    cudaMemsetAsync(out_final, 0, (size_t)T_ * D_ * sizeof(float), 0);
    wconvert_kernel<<<6144, 256>>>(w1, w3, w2);
    prep_kernel<<<1, 256>>>(pad, mid);
    xgate_kernel<<<T_ / 8, 256>>>(x, gw, out_route);
    scan_kernel<<<1, 32>>>();
    ffn1_mma<<<dim3(H_ / 64, E_ * 64), 256, smem>>>(0);
    ffn2_mma<<<dim3(D_ / 128, E_ * 64), 256, smem>>>(out_final, cw);
    clf_kernel<<<1, 32>>>(cb, out_logits);
}

// round 16
// speedup vs baseline: 1.2701x; 1.0169x over previous
#include <cuda_runtime.h>
#include <cuda_fp16.h>
#include <cstdint>

#define T_ 8192
#define D_ 1024
#define H_ 1024
#define E_ 8
#define B_ 4
#define S_ 2048

#define BM 128
#define SSZ 32768u    // stage: A 16KB + B 16KB (BK=64)
#define NCH 16        // 1024 / 64

// ---------------- scratch (no allocation allowed) ----------------
__device__ int g_cnt[E_];
__device__ int g_base[E_];
__device__ int g_btok[E_ * T_];
__device__ float g_bwt[E_ * T_];
__device__ unsigned char g_nonpad[T_];
__device__ float g_invcnt[B_];
__device__ float g_dote[E_ * B_];     // per-(expert,batch) partial dot(mean-sum, clf_w)
// fp16 scratch
__device__ uint16_t g_xf[(size_t)T_ * D_];
__device__ uint16_t g_w1f[(size_t)E_ * D_ * H_];
__device__ uint16_t g_w3f[(size_t)E_ * D_ * H_];
__device__ uint16_t g_w2f[(size_t)E_ * H_ * D_];
__device__ uint16_t g_hactf[(size_t)2 * T_ * H_];

// ================= helpers =================
__device__ __forceinline__ uint32_t smem_u32(const void* p) {
    uint32_t a;
    asm("{ .reg .u64 t; cvta.to.shared.u64 t, %1; cvt.u32.u64 %0, t; }" : "=r"(a) : "l"(p));
    return a;
}
__device__ __forceinline__ uint32_t cvt1h(float f0, float f1) {
    uint32_t h;
    asm("cvt.rn.f16x2.f32 %0, %1, %2;" : "=r"(h) : "f"(f1), "f"(f0));
    return h;
}
__device__ __forceinline__ void cpa16(uint32_t dst, const void* src) {
    asm volatile("cp.async.cg.shared.global [%0], [%1], 16;" :: "r"(dst), "l"(src));
}
#define CP_COMMIT() asm volatile("cp.async.commit_group;")
#define CP_WAIT1() asm volatile("cp.async.wait_group 1;")
__device__ __forceinline__ void ldsm4(uint32_t* r, uint32_t a) {
    asm volatile("ldmatrix.sync.aligned.m8n8.x4.shared.b16 {%0,%1,%2,%3}, [%4];"
                 : "=r"(r[0]), "=r"(r[1]), "=r"(r[2]), "=r"(r[3]) : "r"(a));
}
__device__ __forceinline__ void ldsm4t(uint32_t* r, uint32_t a) {
    asm volatile("ldmatrix.sync.aligned.m8n8.x4.trans.shared.b16 {%0,%1,%2,%3}, [%4];"
                 : "=r"(r[0]), "=r"(r[1]), "=r"(r[2]), "=r"(r[3]) : "r"(a));
}
__device__ __forceinline__ void mma16816h(float* d, const uint32_t* a, uint32_t b0, uint32_t b1) {
    asm volatile(
        "mma.sync.aligned.m16n8k16.row.col.f32.f16.f16.f32 "
        "{%0,%1,%2,%3},{%4,%5,%6,%7},{%8,%9},{%0,%1,%2,%3};"
        : "+f"(d[0]), "+f"(d[1]), "+f"(d[2]), "+f"(d[3])
        : "r"(a[0]), "r"(a[1]), "r"(a[2]), "r"(a[3]), "r"(b0), "r"(b1));
}
// vectorized global reduction (PTX 8.1+, sm_90+): one instruction, two adjacent f32 adds
__device__ __forceinline__ void red2(float* addr, float v0, float v1) {
    asm volatile("red.global.add.v2.f32 [%0], {%1, %2};"
                 :: "l"(addr), "f"(v0), "f"(v1) : "memory");
}
__device__ __forceinline__ uint32_t off128(int r, int u) {
    return (uint32_t)(r * 128 + ((u ^ (r & 7)) << 4));
}
__device__ __forceinline__ uint32_t off256(int r, int u) {
    return (uint32_t)(r * 256 + ((((u ^ r) & 7) | (u & 8)) << 4));
}

// ---------------- fused weight convert: coalesced ILP x4 ----------------
#define SEG_ (2097152u)   // float4 count per tensor
__global__ void wconvert_kernel(const float* __restrict__ w1, const float* __restrict__ w3,
                                const float* __restrict__ w2) {
    uint32_t base = blockIdx.x * 1024 + threadIdx.x;
#pragma unroll
    for (int k = 0; k < 4; k++) {
        uint32_t idx = base + k * 256;
        uint32_t seg = idx / SEG_, off = idx % SEG_;
        const float4* s = (const float4*)((seg == 0) ? w1 : (seg == 1) ? w3 : w2);
        uint2* d = (uint2*)((seg == 0) ? g_w1f : (seg == 1) ? g_w3f : g_w2f);
        float4 v = s[off];
        d[off] = make_uint2(cvt1h(v.x, v.y), cvt1h(v.z, v.w));
    }
}

// ---------------- prep ----------------
__global__ void prep_kernel(const unsigned char* __restrict__ pad,
                            const unsigned char* __restrict__ mid) {
    __shared__ int onebyte;
    __shared__ int cnts[B_];
    int tid = threadIdx.x;
    if (tid == 0) onebyte = 0;
    if (tid < B_) cnts[tid] = 0;
    if (tid < E_) g_cnt[tid] = 0;
    if (tid < E_ * B_) g_dote[tid] = 0.f;
    __syncthreads();
    int found = 0;
    for (int i = tid; i < 2048; i += 256)
        if (pad[4 * i + 1]) found = 1;
    if (found) onebyte = 1;
    __syncthreads();
    bool b1 = (onebyte != 0);
    const unsigned int* pw = (const unsigned int*)pad;
    const unsigned int* mw = (const unsigned int*)mid;
    for (int t = tid; t < T_; t += 256) {
        bool p = b1 ? (pad[t] != 0) : (pw[t] != 0);
        bool m = b1 ? (mid[t] != 0) : (mw[t] != 0);
        unsigned char np = (!p && !m) ? 1 : 0;
        g_nonpad[t] = np;
        if (np) atomicAdd(&cnts[t >> 11], 1);
    }
    __syncthreads();
    if (tid < B_) g_invcnt[tid] = 1.f / (float)cnts[tid];
}

// ---------------- gating + x fp16 conversion (fused) ----------------
__global__ void xgate_kernel(const float* __restrict__ x,
                             const float* __restrict__ gw,
                             float* __restrict__ route_out) {
    int warp = threadIdx.x >> 5, lane = threadIdx.x & 31;
    int t = blockIdx.x * 8 + warp;
    const float* xr = x + (size_t)t * D_;
    float acc[8];
#pragma unroll
    for (int e = 0; e < 8; e++) acc[e] = 0.f;
    for (int d = lane; d < D_; d += 32) {
        float xv = xr[d];
        float4 g0 = *(const float4*)(gw + (size_t)d * 8);
        float4 g1 = *(const float4*)(gw + (size_t)d * 8 + 4);
        acc[0] += xv * g0.x; acc[1] += xv * g0.y;
        acc[2] += xv * g0.z; acc[3] += xv * g0.w;
        acc[4] += xv * g1.x; acc[5] += xv * g1.y;
        acc[6] += xv * g1.z; acc[7] += xv * g1.w;
    }
#pragma unroll
    for (int o = 16; o; o >>= 1)
#pragma unroll
        for (int e = 0; e < 8; e++)
            acc[e] += __shfl_xor_sync(0xffffffffu, acc[e], o);
    if (lane == 0) {
        float mx = acc[0];
#pragma unroll
        for (int e = 1; e < 8; e++) mx = fmaxf(mx, acc[e]);
        float p[8], s = 0.f;
#pragma unroll
        for (int e = 0; e < 8; e++) { p[e] = __expf(acc[e] - mx); s += p[e]; }
        float inv = 1.f / s;
#pragma unroll
        for (int e = 0; e < 8; e++) p[e] *= inv;
        float* ro = route_out + (size_t)t * 8;
#pragma unroll
        for (int e = 0; e < 8; e++) ro[e] = p[e];
        int e0 = 0;
#pragma unroll
        for (int e = 1; e < 8; e++) if (p[e] > p[e0]) e0 = e;
        int e1 = (e0 == 0) ? 1 : 0;
#pragma unroll
        for (int e = 0; e < 8; e++) if (e != e0 && p[e] > p[e1]) e1 = e;
        float inv2 = 1.f / (p[e0] + p[e1]);
        int s0 = atomicAdd(&g_cnt[e0], 1);
        g_btok[e0 * T_ + s0] = t; g_bwt[e0 * T_ + s0] = p[e0] * inv2;
        int s1 = atomicAdd(&g_cnt[e1], 1);
        g_btok[e1 * T_ + s1] = t; g_bwt[e1 * T_ + s1] = p[e1] * inv2;
    }
    // convert this block's 8 token rows to fp16 (reads L1/L2-hot)
    size_t base4 = (size_t)blockIdx.x * 2048;
#pragma unroll
    for (int k = 0; k < 8; k++) {
        size_t i = base4 + threadIdx.x + k * 256;
        float4 v = ((const float4*)x)[i];
        ((uint2*)g_xf)[i] = make_uint2(cvt1h(v.x, v.y), cvt1h(v.z, v.w));
    }
}

__global__ void scan_kernel() {
    if (threadIdx.x == 0) {
        int acc = 0;
        for (int e = 0; e < E_; e++) { g_base[e] = acc; acc += g_cnt[e]; }
    }
}

// ============ ffn1: hact = silu(X@w1)*(X@w3), fp16, BK=64, 3-stage, 2 CTAs/SM ============
__global__ __launch_bounds__(256, 2) void ffn1_mma(int dummy) {
    extern __shared__ char dyn[];
    __shared__ int toks[BM];
    int e = blockIdx.y >> 6, mt = blockIdx.y & 63;
    int cnt = g_cnt[e];
    int row0 = mt * BM;
    if (row0 >= cnt) return;
    int rows = min(BM, cnt - row0);
    int n0 = blockIdx.x * 64;
    int tid = threadIdx.x, wid = tid >> 5, lane = tid & 31;
    if (tid < BM)
        toks[tid] = (tid < rows) ? g_btok[e * T_ + row0 + tid] : g_btok[e * T_ + row0];
    __syncthreads();
    uint32_t sb = (smem_u32(dyn) + 1023u) & ~1023u;

    int am = tid >> 1, ub = (tid & 1) * 4;
    const uint16_t* pA = g_xf + (size_t)toks[am] * D_ + (tid & 1) * 32;
    uint32_t dA[4] = { off128(am, ub), off128(am, ub + 1), off128(am, ub + 2), off128(am, ub + 3) };
    int bk = tid >> 2, bu = (tid & 3) * 2;
    size_t woff = ((size_t)e * D_ + bk) * H_ + n0 + bu * 8;
    const uint16_t* p1 = g_w1f + woff;
    const uint16_t* p3 = g_w3f + woff;
    uint32_t dB0 = off128(bk, bu), dB1 = off128(bk, bu + 1);

    auto issue = [&](int c) {
        uint32_t st = sb + (uint32_t)(c % 3) * SSZ;
        const uint16_t* a = pA + c * 64;
#pragma unroll
        for (int j = 0; j < 4; j++) cpa16(st + dA[j], a + j * 8);
        size_t wo = (size_t)c * 64 * H_;
        cpa16(st + 16384u + dB0, p1 + wo);
        cpa16(st + 16384u + dB1, p1 + wo + 8);
        cpa16(st + 24576u + dB0, p3 + wo);
        cpa16(st + 24576u + dB1, p3 + wo + 8);
        CP_COMMIT();
    };

    float acc1[2][4][4], acc3[2][4][4];
#pragma unroll
    for (int a = 0; a < 2; a++)
#pragma unroll
        for (int b = 0; b < 4; b++)
#pragma unroll
            for (int q = 0; q < 4; q++) { acc1[a][b][q] = 0.f; acc3[a][b][q] = 0.f; }

    int lr = (lane & 7) + ((lane >> 3) & 1) * 8;
    int uo = (lane >> 4) & 1;
    int mq = wid & 3, nh = wid >> 2;

    issue(0); issue(1);
    for (int c = 0; c < NCH; c++) {
        CP_WAIT1();
        __syncthreads();
        if (c + 2 < NCH) issue(c + 2); else CP_COMMIT();
        uint32_t base = sb + (uint32_t)(c % 3) * SSZ;
        uint32_t aT = base, w1T = base + 16384u, w3T = base + 24576u;
#pragma unroll
        for (int kb = 0; kb < 4; kb++) {
            uint32_t A[2][4];
#pragma unroll
            for (int mb = 0; mb < 2; mb++)
                ldsm4(A[mb], aT + off128(mq * 32 + mb * 16 + lr, kb * 2 + uo));
            int krow = kb * 16 + lr;
#pragma unroll
            for (int nb = 0; nb < 2; nb++) {
                uint32_t so = off128(krow, nh * 4 + nb * 2 + uo);
                uint32_t F[4];
                ldsm4t(F, w1T + so);
#pragma unroll
                for (int mb = 0; mb < 2; mb++) {
                    mma16816h(acc1[mb][nb * 2 + 0], A[mb], F[0], F[1]);
                    mma16816h(acc1[mb][nb * 2 + 1], A[mb], F[2], F[3]);
                }
                ldsm4t(F, w3T + so);
#pragma unroll
                for (int mb = 0; mb < 2; mb++) {
                    mma16816h(acc3[mb][nb * 2 + 0], A[mb], F[0], F[1]);
                    mma16816h(acc3[mb][nb * 2 + 1], A[mb], F[2], F[3]);
                }
            }
        }
    }
    int gbase = g_base[e] + row0;
    int r0c = lane >> 2, cc = 2 * (lane & 3);
#pragma unroll
    for (int mb = 0; mb < 2; mb++)
#pragma unroll
        for (int nf = 0; nf < 4; nf++) {
            int col = n0 + nh * 32 + nf * 8 + cc;
#pragma unroll
            for (int hrow = 0; hrow < 2; hrow++) {
                int m0 = mq * 32 + mb * 16 + r0c + hrow * 8;
                if (m0 < rows) {
                    float a0 = acc1[mb][nf][hrow * 2],     b0 = acc3[mb][nf][hrow * 2];
                    float a1 = acc1[mb][nf][hrow * 2 + 1], b1 = acc3[mb][nf][hrow * 2 + 1];
                    float o0 = a0 / (1.f + __expf(-a0)) * b0;
                    float o1 = a1 / (1.f + __expf(-a1)) * b1;
                    size_t off = ((size_t)(gbase + m0) * H_ + col) >> 1;
                    ((uint32_t*)g_hactf)[off] = cvt1h(o0, o1);
                }
            }
        }
}

// ============ ffn2: Y = hact @ w2, fp16, BK=64, 3-stage, 2 CTAs/SM, scatter ============
// final-output scatter uses red.global.add.v2.f32 (one instruction per adjacent pair);
// classifier path via scalar dot partials (R15 scheme).
__global__ __launch_bounds__(256, 2) void ffn2_mma(float* __restrict__ outF,
                                                   const float* __restrict__ clf_w) {
    extern __shared__ char dyn[];
    __shared__ int toks[BM];
    __shared__ float wts[BM];
    __shared__ float sdot[B_];
    int e = blockIdx.y >> 6, mt = blockIdx.y & 63;
    int cnt = g_cnt[e];
    int row0 = mt * BM;
    if (row0 >= cnt) return;
    int rows = min(BM, cnt - row0);
    int n0 = blockIdx.x * 128;
    int tid = threadIdx.x, wid = tid >> 5, lane = tid & 31;
    if (tid < BM) {
        int idx = e * T_ + row0 + tid;
        toks[tid] = (tid < rows) ? g_btok[idx] : 0;
        wts[tid] = (tid < rows) ? g_bwt[idx] : 0.f;
    }
    if (tid < B_) sdot[tid] = 0.f;
    __syncthreads();
    uint32_t sb = (smem_u32(dyn) + 1023u) & ~1023u;
    int gbase = g_base[e] + row0;

    int am = tid >> 1, ub = (tid & 1) * 4;
    const uint16_t* pA = g_hactf + (size_t)(gbase + min(am, rows - 1)) * H_ + (tid & 1) * 32;
    uint32_t dA[4] = { off128(am, ub), off128(am, ub + 1), off128(am, ub + 2), off128(am, ub + 3) };
    int bk = tid >> 2, bu4 = (tid & 3) * 4;
    size_t woff = ((size_t)e * H_ + bk) * D_ + n0 + bu4 * 8;
    const uint16_t* p2 = g_w2f + woff;
    uint32_t dB[4] = { off256(bk, bu4), off256(bk, bu4 + 1), off256(bk, bu4 + 2), off256(bk, bu4 + 3) };

    auto issue = [&](int c) {
        uint32_t st = sb + (uint32_t)(c % 3) * SSZ;
        const uint16_t* a = pA + c * 64;
#pragma unroll
        for (int j = 0; j < 4; j++) cpa16(st + dA[j], a + j * 8);
        size_t wo = (size_t)c * 64 * D_;
#pragma unroll
        for (int j = 0; j < 4; j++) cpa16(st + 16384u + dB[j], p2 + wo + j * 8);
        CP_COMMIT();
    };

    float acc[2][8][4];
#pragma unroll
    for (int a = 0; a < 2; a++)
#pragma unroll
        for (int b = 0; b < 8; b++)
#pragma unroll
            for (int q = 0; q < 4; q++) acc[a][b][q] = 0.f;

    int lr = (lane & 7) + ((lane >> 3) & 1) * 8;
    int uo = (lane >> 4) & 1;
    int mq = wid & 3, nh = wid >> 2;

    issue(0); issue(1);
    for (int c = 0; c < NCH; c++) {
        CP_WAIT1();
        __syncthreads();
        if (c + 2 < NCH) issue(c + 2); else CP_COMMIT();
        uint32_t base = sb + (uint32_t)(c % 3) * SSZ;
        uint32_t aT = base, w2T = base + 16384u;
#pragma unroll
        for (int kb = 0; kb < 4; kb++) {
            uint32_t A[2][4];
#pragma unroll
            for (int mb = 0; mb < 2; mb++)
                ldsm4(A[mb], aT + off128(mq * 32 + mb * 16 + lr, kb * 2 + uo));
            int krow = kb * 16 + lr;
#pragma unroll
            for (int nb = 0; nb < 4; nb++) {
                uint32_t F[4];
                ldsm4t(F, w2T + off256(krow, nh * 8 + nb * 2 + uo));
#pragma unroll
                for (int mb = 0; mb < 2; mb++) {
                    mma16816h(acc[mb][nb * 2 + 0], A[mb], F[0], F[1]);
                    mma16816h(acc[mb][nb * 2 + 1], A[mb], F[2], F[3]);
                }
            }
        }
    }
    // epilogue: scale, v2-RED scatter to outF, accumulate clf dot partials per batch
    int r0c = lane >> 2, cc = 2 * (lane & 3);
    float db0 = 0.f, db1 = 0.f, db2 = 0.f, db3 = 0.f;
#pragma unroll
    for (int mb = 0; mb < 2; mb++)
#pragma unroll
        for (int nf = 0; nf < 8; nf++) {
            int col = n0 + nh * 64 + nf * 8 + cc;
            float cw0 = __ldg(clf_w + col);
            float cw1 = __ldg(clf_w + col + 1);
#pragma unroll
            for (int hrow = 0; hrow < 2; hrow++) {
                int m0 = mq * 32 + mb * 16 + r0c + hrow * 8;
                if (m0 < rows) {
                    int t = toks[m0];
                    float wt = wts[m0];
                    float v0 = wt * acc[mb][nf][hrow * 2];
                    float v1 = wt * acc[mb][nf][hrow * 2 + 1];
                    red2(outF + (size_t)t * D_ + col, v0, v1);
                    if (g_nonpad[t]) {
                        float p = v0 * cw0 + v1 * cw1;
                        int bb = t >> 11;
                        db0 += (bb == 0) ? p : 0.f;
                        db1 += (bb == 1) ? p : 0.f;
                        db2 += (bb == 2) ? p : 0.f;
                        db3 += (bb == 3) ? p : 0.f;
                    }
                }
            }
        }
    // warp-reduce 4 batch partials, one smem add per warp, 4 global atomics per CTA
    float db[4] = { db0, db1, db2, db3 };
#pragma unroll
    for (int j = 0; j < 4; j++) {
        float v = db[j];
#pragma unroll
        for (int o = 16; o; o >>= 1) v += __shfl_xor_sync(0xffffffffu, v, o);
        if (lane == 0 && v != 0.f) atomicAdd(&sdot[j], v);
    }
    __syncthreads();
    if (tid < B_) {
        float v = sdot[tid];
        if (v != 0.f) atomicAdd(&g_dote[e * B_ + tid], v);
    }
}

// ---------------- classifier (cumsum of precomputed dots) ----------------
__global__ void clf_kernel(const float* __restrict__ clf_b,
                           float* __restrict__ outL) {
    int tid = threadIdx.x;
    if (tid < E_ * B_) {
        int e = tid >> 2, b = tid & 3;
        float c = 0.f;
        for (int ee = 0; ee <= e; ee++) c += g_dote[ee * B_ + b];
        outL[e * B_ + b] = c * g_invcnt[b] + clf_b[0];
    }
}

// ---------------- launch ----------------
extern "C" void kernel_launch(void* const* d_in, const int* in_sizes, int n_in,
                              void* d_out, int out_size) {
    int base = 4;
    if (n_in == 9 || (n_in > 3 && in_sizes[3] != 1)) base = 3;
    const float* x = (const float*)d_in[0];
    const unsigned char* pad = (const unsigned char*)d_in[1];
    const unsigned char* mid = (const unsigned char*)d_in[2];
    const float* gw = (const float*)d_in[base + 0];
    const float* w1 = (const float*)d_in[base + 1];
    const float* w2 = (const float*)d_in[base + 2];
    const float* w3 = (const float*)d_in[base + 3];
    const float* cw = (const float*)d_in[base + 4];
    const float* cb = (const float*)d_in[base + 5];
    float* out = (float*)d_out;

    float* out_final = out;
    float* out_logits = out + (size_t)T_ * D_;
    float* out_route = out + (size_t)T_ * D_ + E_ * B_;

    const int smem = 3 * (int)SSZ + 1024;   // 99328 -> 2 CTAs/SM
    cudaFuncSetAttribute(ffn1_mma, cudaFuncAttributeMaxDynamicSharedMemorySize, smem);
    cudaFuncSetAttribute(ffn2_mma, cudaFuncAttributeMaxDynamicSharedMemorySize, smem);

    cudaMemsetAsync(out_final, 0, (size_t)T_ * D_ * sizeof(float), 0);
    wconvert_kernel<<<6144, 256>>>(w1, w3, w2);
    prep_kernel<<<1, 256>>>(pad, mid);
    xgate_kernel<<<T_ / 8, 256>>>(x, gw, out_route);
    scan_kernel<<<1, 32>>>();
    ffn1_mma<<<dim3(H_ / 64, E_ * 64), 256, smem>>>(0);
    ffn2_mma<<<dim3(D_ / 128, E_ * 64), 256, smem>>>(out_final, cw);
    clf_kernel<<<1, 32>>>(cb, out_logits);
}

// round 17
// speedup vs baseline: 1.2755x; 1.0042x over previous
#include <cuda_runtime.h>
#include <cuda_fp16.h>
#include <cstdint>

#define T_ 8192
#define D_ 1024
#define H_ 1024
#define E_ 8
#define B_ 4
#define S_ 2048

#define BM 128
#define SSZ 32768u    // stage: A 16KB + B 16KB (BK=64)
#define NCH 16        // 1024 / 64

// ---------------- scratch (no allocation allowed) ----------------
__device__ int g_cnt[E_];
__device__ int g_btok[E_ * T_];
__device__ float g_bwt[E_ * T_];
__device__ unsigned char g_nonpad[T_];
__device__ float g_invcnt[B_];
__device__ float g_dote[E_ * B_];     // per-(expert,batch) partial dot with clf_w
// fp16 scratch
__device__ uint16_t g_xf[(size_t)T_ * D_];
__device__ uint16_t g_w1f[(size_t)E_ * D_ * H_];
__device__ uint16_t g_w3f[(size_t)E_ * D_ * H_];
__device__ uint16_t g_w2f[(size_t)E_ * H_ * D_];
// static per-expert regions: expert e owns rows [e*T_, e*T_+cnt[e])  (128 MB)
__device__ uint16_t g_hactf[(size_t)E_ * T_ * H_];

// ================= helpers =================
__device__ __forceinline__ uint32_t smem_u32(const void* p) {
    uint32_t a;
    asm("{ .reg .u64 t; cvta.to.shared.u64 t, %1; cvt.u32.u64 %0, t; }" : "=r"(a) : "l"(p));
    return a;
}
__device__ __forceinline__ uint32_t cvt1h(float f0, float f1) {
    uint32_t h;
    asm("cvt.rn.f16x2.f32 %0, %1, %2;" : "=r"(h) : "f"(f1), "f"(f0));
    return h;
}
__device__ __forceinline__ void cpa16(uint32_t dst, const void* src) {
    asm volatile("cp.async.cg.shared.global [%0], [%1], 16;" :: "r"(dst), "l"(src));
}
#define CP_COMMIT() asm volatile("cp.async.commit_group;")
#define CP_WAIT1() asm volatile("cp.async.wait_group 1;")
__device__ __forceinline__ void ldsm4(uint32_t* r, uint32_t a) {
    asm volatile("ldmatrix.sync.aligned.m8n8.x4.shared.b16 {%0,%1,%2,%3}, [%4];"
                 : "=r"(r[0]), "=r"(r[1]), "=r"(r[2]), "=r"(r[3]) : "r"(a));
}
__device__ __forceinline__ void ldsm4t(uint32_t* r, uint32_t a) {
    asm volatile("ldmatrix.sync.aligned.m8n8.x4.trans.shared.b16 {%0,%1,%2,%3}, [%4];"
                 : "=r"(r[0]), "=r"(r[1]), "=r"(r[2]), "=r"(r[3]) : "r"(a));
}
__device__ __forceinline__ void mma16816h(float* d, const uint32_t* a, uint32_t b0, uint32_t b1) {
    asm volatile(
        "mma.sync.aligned.m16n8k16.row.col.f32.f16.f16.f32 "
        "{%0,%1,%2,%3},{%4,%5,%6,%7},{%8,%9},{%0,%1,%2,%3};"
        : "+f"(d[0]), "+f"(d[1]), "+f"(d[2]), "+f"(d[3])
        : "r"(a[0]), "r"(a[1]), "r"(a[2]), "r"(a[3]), "r"(b0), "r"(b1));
}
// vectorized global reduction (PTX 8.1+, sm_90+)
__device__ __forceinline__ void red2(float* addr, float v0, float v1) {
    asm volatile("red.global.add.v2.f32 [%0], {%1, %2};"
                 :: "l"(addr), "f"(v0), "f"(v1) : "memory");
}
__device__ __forceinline__ uint32_t off128(int r, int u) {
    return (uint32_t)(r * 128 + ((u ^ (r & 7)) << 4));
}
__device__ __forceinline__ uint32_t off256(int r, int u) {
    return (uint32_t)(r * 256 + ((((u ^ r) & 7) | (u & 8)) << 4));
}

// ---------------- fused weight convert: coalesced ILP x4 ----------------
#define SEG_ (2097152u)   // float4 count per tensor
__global__ void wconvert_kernel(const float* __restrict__ w1, const float* __restrict__ w3,
                                const float* __restrict__ w2) {
    uint32_t base = blockIdx.x * 1024 + threadIdx.x;
#pragma unroll
    for (int k = 0; k < 4; k++) {
        uint32_t idx = base + k * 256;
        uint32_t seg = idx / SEG_, off = idx % SEG_;
        const float4* s = (const float4*)((seg == 0) ? w1 : (seg == 1) ? w3 : w2);
        uint2* d = (uint2*)((seg == 0) ? g_w1f : (seg == 1) ? g_w3f : g_w2f);
        float4 v = s[off];
        d[off] = make_uint2(cvt1h(v.x, v.y), cvt1h(v.z, v.w));
    }
}

// ---------------- prep ----------------
__global__ void prep_kernel(const unsigned char* __restrict__ pad,
                            const unsigned char* __restrict__ mid) {
    __shared__ int onebyte;
    __shared__ int cnts[B_];
    int tid = threadIdx.x;
    if (tid == 0) onebyte = 0;
    if (tid < B_) cnts[tid] = 0;
    if (tid < E_) g_cnt[tid] = 0;
    if (tid < E_ * B_) g_dote[tid] = 0.f;
    __syncthreads();
    int found = 0;
    for (int i = tid; i < 2048; i += 256)
        if (pad[4 * i + 1]) found = 1;
    if (found) onebyte = 1;
    __syncthreads();
    bool b1 = (onebyte != 0);
    const unsigned int* pw = (const unsigned int*)pad;
    const unsigned int* mw = (const unsigned int*)mid;
    for (int t = tid; t < T_; t += 256) {
        bool p = b1 ? (pad[t] != 0) : (pw[t] != 0);
        bool m = b1 ? (mid[t] != 0) : (mw[t] != 0);
        unsigned char np = (!p && !m) ? 1 : 0;
        g_nonpad[t] = np;
        if (np) atomicAdd(&cnts[t >> 11], 1);
    }
    __syncthreads();
    if (tid < B_) g_invcnt[tid] = 1.f / (float)cnts[tid];
}

// ---------------- gating + x fp16 conversion (fused) ----------------
__global__ void xgate_kernel(const float* __restrict__ x,
                             const float* __restrict__ gw,
                             float* __restrict__ route_out) {
    int warp = threadIdx.x >> 5, lane = threadIdx.x & 31;
    int t = blockIdx.x * 8 + warp;
    const float* xr = x + (size_t)t * D_;
    float acc[8];
#pragma unroll
    for (int e = 0; e < 8; e++) acc[e] = 0.f;
    for (int d = lane; d < D_; d += 32) {
        float xv = xr[d];
        float4 g0 = *(const float4*)(gw + (size_t)d * 8);
        float4 g1 = *(const float4*)(gw + (size_t)d * 8 + 4);
        acc[0] += xv * g0.x; acc[1] += xv * g0.y;
        acc[2] += xv * g0.z; acc[3] += xv * g0.w;
        acc[4] += xv * g1.x; acc[5] += xv * g1.y;
        acc[6] += xv * g1.z; acc[7] += xv * g1.w;
    }
#pragma unroll
    for (int o = 16; o; o >>= 1)
#pragma unroll
        for (int e = 0; e < 8; e++)
            acc[e] += __shfl_xor_sync(0xffffffffu, acc[e], o);
    if (lane == 0) {
        float mx = acc[0];
#pragma unroll
        for (int e = 1; e < 8; e++) mx = fmaxf(mx, acc[e]);
        float p[8], s = 0.f;
#pragma unroll
        for (int e = 0; e < 8; e++) { p[e] = __expf(acc[e] - mx); s += p[e]; }
        float inv = 1.f / s;
#pragma unroll
        for (int e = 0; e < 8; e++) p[e] *= inv;
        float* ro = route_out + (size_t)t * 8;
#pragma unroll
        for (int e = 0; e < 8; e++) ro[e] = p[e];
        int e0 = 0;
#pragma unroll
        for (int e = 1; e < 8; e++) if (p[e] > p[e0]) e0 = e;
        int e1 = (e0 == 0) ? 1 : 0;
#pragma unroll
        for (int e = 0; e < 8; e++) if (e != e0 && p[e] > p[e1]) e1 = e;
        float inv2 = 1.f / (p[e0] + p[e1]);
        int s0 = atomicAdd(&g_cnt[e0], 1);
        g_btok[e0 * T_ + s0] = t; g_bwt[e0 * T_ + s0] = p[e0] * inv2;
        int s1 = atomicAdd(&g_cnt[e1], 1);
        g_btok[e1 * T_ + s1] = t; g_bwt[e1 * T_ + s1] = p[e1] * inv2;
    }
    // convert this block's 8 token rows to fp16 (reads L1/L2-hot)
    size_t base4 = (size_t)blockIdx.x * 2048;
#pragma unroll
    for (int k = 0; k < 8; k++) {
        size_t i = base4 + threadIdx.x + k * 256;
        float4 v = ((const float4*)x)[i];
        ((uint2*)g_xf)[i] = make_uint2(cvt1h(v.x, v.y), cvt1h(v.z, v.w));
    }
}

// ============ ffn1: hact = silu(X@w1)*(X@w3), fp16, BK=64, 3-stage, 2 CTAs/SM ============
__global__ __launch_bounds__(256, 2) void ffn1_mma(int dummy) {
    extern __shared__ char dyn[];
    __shared__ int toks[BM];
    int e = blockIdx.y >> 6, mt = blockIdx.y & 63;
    int cnt = g_cnt[e];
    int row0 = mt * BM;
    if (row0 >= cnt) return;
    int rows = min(BM, cnt - row0);
    int n0 = blockIdx.x * 64;
    int tid = threadIdx.x, wid = tid >> 5, lane = tid & 31;
    if (tid < BM)
        toks[tid] = (tid < rows) ? g_btok[e * T_ + row0 + tid] : g_btok[e * T_ + row0];
    __syncthreads();
    uint32_t sb = (smem_u32(dyn) + 1023u) & ~1023u;

    int am = tid >> 1, ub = (tid & 1) * 4;
    const uint16_t* pA = g_xf + (size_t)toks[am] * D_ + (tid & 1) * 32;
    uint32_t dA[4] = { off128(am, ub), off128(am, ub + 1), off128(am, ub + 2), off128(am, ub + 3) };
    int bk = tid >> 2, bu = (tid & 3) * 2;
    size_t woff = ((size_t)e * D_ + bk) * H_ + n0 + bu * 8;
    const uint16_t* p1 = g_w1f + woff;
    const uint16_t* p3 = g_w3f + woff;
    uint32_t dB0 = off128(bk, bu), dB1 = off128(bk, bu + 1);

    auto issue = [&](int c) {
        uint32_t st = sb + (uint32_t)(c % 3) * SSZ;
        const uint16_t* a = pA + c * 64;
#pragma unroll
        for (int j = 0; j < 4; j++) cpa16(st + dA[j], a + j * 8);
        size_t wo = (size_t)c * 64 * H_;
        cpa16(st + 16384u + dB0, p1 + wo);
        cpa16(st + 16384u + dB1, p1 + wo + 8);
        cpa16(st + 24576u + dB0, p3 + wo);
        cpa16(st + 24576u + dB1, p3 + wo + 8);
        CP_COMMIT();
    };

    float acc1[2][4][4], acc3[2][4][4];
#pragma unroll
    for (int a = 0; a < 2; a++)
#pragma unroll
        for (int b = 0; b < 4; b++)
#pragma unroll
            for (int q = 0; q < 4; q++) { acc1[a][b][q] = 0.f; acc3[a][b][q] = 0.f; }

    int lr = (lane & 7) + ((lane >> 3) & 1) * 8;
    int uo = (lane >> 4) & 1;
    int mq = wid & 3, nh = wid >> 2;

    issue(0); issue(1);
    for (int c = 0; c < NCH; c++) {
        CP_WAIT1();
        __syncthreads();
        if (c + 2 < NCH) issue(c + 2); else CP_COMMIT();
        uint32_t base = sb + (uint32_t)(c % 3) * SSZ;
        uint32_t aT = base, w1T = base + 16384u, w3T = base + 24576u;
#pragma unroll
        for (int kb = 0; kb < 4; kb++) {
            uint32_t A[2][4];
#pragma unroll
            for (int mb = 0; mb < 2; mb++)
                ldsm4(A[mb], aT + off128(mq * 32 + mb * 16 + lr, kb * 2 + uo));
            int krow = kb * 16 + lr;
#pragma unroll
            for (int nb = 0; nb < 2; nb++) {
                uint32_t so = off128(krow, nh * 4 + nb * 2 + uo);
                uint32_t F[4];
                ldsm4t(F, w1T + so);
#pragma unroll
                for (int mb = 0; mb < 2; mb++) {
                    mma16816h(acc1[mb][nb * 2 + 0], A[mb], F[0], F[1]);
                    mma16816h(acc1[mb][nb * 2 + 1], A[mb], F[2], F[3]);
                }
                ldsm4t(F, w3T + so);
#pragma unroll
                for (int mb = 0; mb < 2; mb++) {
                    mma16816h(acc3[mb][nb * 2 + 0], A[mb], F[0], F[1]);
                    mma16816h(acc3[mb][nb * 2 + 1], A[mb], F[2], F[3]);
                }
            }
        }
    }
    // epilogue: static expert region, no prefix scan needed
    size_t gbase = (size_t)e * T_ + row0;
    int r0c = lane >> 2, cc = 2 * (lane & 3);
#pragma unroll
    for (int mb = 0; mb < 2; mb++)
#pragma unroll
        for (int nf = 0; nf < 4; nf++) {
            int col = n0 + nh * 32 + nf * 8 + cc;
#pragma unroll
            for (int hrow = 0; hrow < 2; hrow++) {
                int m0 = mq * 32 + mb * 16 + r0c + hrow * 8;
                if (m0 < rows) {
                    float a0 = acc1[mb][nf][hrow * 2],     b0 = acc3[mb][nf][hrow * 2];
                    float a1 = acc1[mb][nf][hrow * 2 + 1], b1 = acc3[mb][nf][hrow * 2 + 1];
                    float o0 = a0 / (1.f + __expf(-a0)) * b0;
                    float o1 = a1 / (1.f + __expf(-a1)) * b1;
                    size_t off = ((gbase + m0) * H_ + col) >> 1;
                    ((uint32_t*)g_hactf)[off] = cvt1h(o0, o1);
                }
            }
        }
}

// ============ ffn2: Y = hact @ w2, fp16, BK=64, 3-stage, 2 CTAs/SM, v2-RED scatter ============
__global__ __launch_bounds__(256, 2) void ffn2_mma(float* __restrict__ outF,
                                                   const float* __restrict__ clf_w) {
    extern __shared__ char dyn[];
    __shared__ int toks[BM];
    __shared__ float wts[BM];
    __shared__ float sdot[B_];
    int e = blockIdx.y >> 6, mt = blockIdx.y & 63;
    int cnt = g_cnt[e];
    int row0 = mt * BM;
    if (row0 >= cnt) return;
    int rows = min(BM, cnt - row0);
    int n0 = blockIdx.x * 128;
    int tid = threadIdx.x, wid = tid >> 5, lane = tid & 31;
    if (tid < BM) {
        int idx = e * T_ + row0 + tid;
        toks[tid] = (tid < rows) ? g_btok[idx] : 0;
        wts[tid] = (tid < rows) ? g_bwt[idx] : 0.f;
    }
    if (tid < B_) sdot[tid] = 0.f;
    __syncthreads();
    uint32_t sb = (smem_u32(dyn) + 1023u) & ~1023u;
    size_t gbase = (size_t)e * T_ + row0;

    int am = tid >> 1, ub = (tid & 1) * 4;
    const uint16_t* pA = g_hactf + (gbase + min(am, rows - 1)) * H_ + (tid & 1) * 32;
    uint32_t dA[4] = { off128(am, ub), off128(am, ub + 1), off128(am, ub + 2), off128(am, ub + 3) };
    int bk = tid >> 2, bu4 = (tid & 3) * 4;
    size_t woff = ((size_t)e * H_ + bk) * D_ + n0 + bu4 * 8;
    const uint16_t* p2 = g_w2f + woff;
    uint32_t dB[4] = { off256(bk, bu4), off256(bk, bu4 + 1), off256(bk, bu4 + 2), off256(bk, bu4 + 3) };

    auto issue = [&](int c) {
        uint32_t st = sb + (uint32_t)(c % 3) * SSZ;
        const uint16_t* a = pA + c * 64;
#pragma unroll
        for (int j = 0; j < 4; j++) cpa16(st + dA[j], a + j * 8);
        size_t wo = (size_t)c * 64 * D_;
#pragma unroll
        for (int j = 0; j < 4; j++) cpa16(st + 16384u + dB[j], p2 + wo + j * 8);
        CP_COMMIT();
    };

    float acc[2][8][4];
#pragma unroll
    for (int a = 0; a < 2; a++)
#pragma unroll
        for (int b = 0; b < 8; b++)
#pragma unroll
            for (int q = 0; q < 4; q++) acc[a][b][q] = 0.f;

    int lr = (lane & 7) + ((lane >> 3) & 1) * 8;
    int uo = (lane >> 4) & 1;
    int mq = wid & 3, nh = wid >> 2;

    issue(0); issue(1);
    for (int c = 0; c < NCH; c++) {
        CP_WAIT1();
        __syncthreads();
        if (c + 2 < NCH) issue(c + 2); else CP_COMMIT();
        uint32_t base = sb + (uint32_t)(c % 3) * SSZ;
        uint32_t aT = base, w2T = base + 16384u;
#pragma unroll
        for (int kb = 0; kb < 4; kb++) {
            uint32_t A[2][4];
#pragma unroll
            for (int mb = 0; mb < 2; mb++)
                ldsm4(A[mb], aT + off128(mq * 32 + mb * 16 + lr, kb * 2 + uo));
            int krow = kb * 16 + lr;
#pragma unroll
            for (int nb = 0; nb < 4; nb++) {
                uint32_t F[4];
                ldsm4t(F, w2T + off256(krow, nh * 8 + nb * 2 + uo));
#pragma unroll
                for (int mb = 0; mb < 2; mb++) {
                    mma16816h(acc[mb][nb * 2 + 0], A[mb], F[0], F[1]);
                    mma16816h(acc[mb][nb * 2 + 1], A[mb], F[2], F[3]);
                }
            }
        }
    }
    // epilogue: scale, v2-RED scatter to outF, accumulate clf dot partials per batch
    int r0c = lane >> 2, cc = 2 * (lane & 3);
    float db0 = 0.f, db1 = 0.f, db2 = 0.f, db3 = 0.f;
#pragma unroll
    for (int mb = 0; mb < 2; mb++)
#pragma unroll
        for (int nf = 0; nf < 8; nf++) {
            int col = n0 + nh * 64 + nf * 8 + cc;
            float cw0 = __ldg(clf_w + col);
            float cw1 = __ldg(clf_w + col + 1);
#pragma unroll
            for (int hrow = 0; hrow < 2; hrow++) {
                int m0 = mq * 32 + mb * 16 + r0c + hrow * 8;
                if (m0 < rows) {
                    int t = toks[m0];
                    float wt = wts[m0];
                    float v0 = wt * acc[mb][nf][hrow * 2];
                    float v1 = wt * acc[mb][nf][hrow * 2 + 1];
                    red2(outF + (size_t)t * D_ + col, v0, v1);
                    if (g_nonpad[t]) {
                        float p = v0 * cw0 + v1 * cw1;
                        int bb = t >> 11;
                        db0 += (bb == 0) ? p : 0.f;
                        db1 += (bb == 1) ? p : 0.f;
                        db2 += (bb == 2) ? p : 0.f;
                        db3 += (bb == 3) ? p : 0.f;
                    }
                }
            }
        }
    float db[4] = { db0, db1, db2, db3 };
#pragma unroll
    for (int j = 0; j < 4; j++) {
        float v = db[j];
#pragma unroll
        for (int o = 16; o; o >>= 1) v += __shfl_xor_sync(0xffffffffu, v, o);
        if (lane == 0 && v != 0.f) atomicAdd(&sdot[j], v);
    }
    __syncthreads();
    if (tid < B_) {
        float v = sdot[tid];
        if (v != 0.f) atomicAdd(&g_dote[e * B_ + tid], v);
    }
}

// ---------------- classifier (cumsum of precomputed dots) ----------------
__global__ void clf_kernel(const float* __restrict__ clf_b,
                           float* __restrict__ outL) {
    int tid = threadIdx.x;
    if (tid < E_ * B_) {
        int e = tid >> 2, b = tid & 3;
        float c = 0.f;
        for (int ee = 0; ee <= e; ee++) c += g_dote[ee * B_ + b];
        outL[e * B_ + b] = c * g_invcnt[b] + clf_b[0];
    }
}

// ---------------- launch ----------------
extern "C" void kernel_launch(void* const* d_in, const int* in_sizes, int n_in,
                              void* d_out, int out_size) {
    int base = 4;
    if (n_in == 9 || (n_in > 3 && in_sizes[3] != 1)) base = 3;
    const float* x = (const float*)d_in[0];
    const unsigned char* pad = (const unsigned char*)d_in[1];
    const unsigned char* mid = (const unsigned char*)d_in[2];
    const float* gw = (const float*)d_in[base + 0];
    const float* w1 = (const float*)d_in[base + 1];
    const float* w2 = (const float*)d_in[base + 2];
    const float* w3 = (const float*)d_in[base + 3];
    const float* cw = (const float*)d_in[base + 4];
    const float* cb = (const float*)d_in[base + 5];
    float* out = (float*)d_out;

    float* out_final = out;
    float* out_logits = out + (size_t)T_ * D_;
    float* out_route = out + (size_t)T_ * D_ + E_ * B_;

    const int smem = 3 * (int)SSZ + 1024;   // 99328 -> 2 CTAs/SM
    cudaFuncSetAttribute(ffn1_mma, cudaFuncAttributeMaxDynamicSharedMemorySize, smem);
    cudaFuncSetAttribute(ffn2_mma, cudaFuncAttributeMaxDynamicSharedMemorySize, smem);

    cudaMemsetAsync(out_final, 0, (size_t)T_ * D_ * sizeof(float), 0);
    wconvert_kernel<<<6144, 256>>>(w1, w3, w2);
    prep_kernel<<<1, 256>>>(pad, mid);
    xgate_kernel<<<T_ / 8, 256>>>(x, gw, out_route);
    ffn1_mma<<<dim3(H_ / 64, E_ * 64), 256, smem>>>(0);
    ffn2_mma<<<dim3(D_ / 128, E_ * 64), 256, smem>>>(out_final, cw);
    clf_kernel<<<1, 32>>>(cb, out_logits);
}